// round 7
// baseline (speedup 1.0000x reference)
#include <cuda_runtime.h>
#include <cuda_bf16.h>

// Problem constants (fixed by reference setup_inputs)
#define BATCH   2
#define SEQ     2048
#define DIN     1024
#define DOUT    1024
#define NHEADS  16
#define HDIM    64
#define MROWS   (BATCH * SEQ)        // 4096

// ---------------------------------------------------------------------------
// Scratch (device globals — no runtime allocation allowed)
// ---------------------------------------------------------------------------
__device__ float g_Q[MROWS * DOUT];
__device__ float g_K[MROWS * DOUT];
__device__ float g_V[MROWS * DOUT];
__device__ float g_CTX[MROWS * DOUT];

// ---------------------------------------------------------------------------
// SGEMM: C[M,N] = A[M,K] @ B[K,N] (+ bias), all row-major fp32.
// Block tile 128x128, K-tile 8, 256 threads, 8x8 per thread.
// M,N,K all multiples of the tiles for this problem -> no bounds checks.
// ---------------------------------------------------------------------------
#define GBM 128
#define GBN 128
#define GBK 8

__global__ __launch_bounds__(256)
void sgemm_kernel(const float* __restrict__ A, const float* __restrict__ B,
                  const float* __restrict__ bias, float* __restrict__ C,
                  int M, int N, int K)
{
    __shared__ __align__(16) float As[GBK][GBM];   // transposed A tile
    __shared__ __align__(16) float Bs[GBK][GBN];

    const int tid = threadIdx.x;
    const int tx  = tid & 15;          // 0..15 (N dir)
    const int ty  = tid >> 4;          // 0..15 (M dir)
    const int bm  = blockIdx.y * GBM;
    const int bn  = blockIdx.x * GBN;

    // A tile loader: one float4 per thread: row = tid/2, cols = (tid&1)*4..+3
    const int arow = tid >> 1;
    const int acol = (tid & 1) << 2;
    // B tile loader: row = tid/32, cols = (tid&31)*4..+3
    const int brow = tid >> 5;
    const int bcol = (tid & 31) << 2;

    const float* Aptr = A + (size_t)(bm + arow) * K + acol;
    const float* Bptr = B + (size_t)brow * N + bn + bcol;

    float acc[8][8];
    #pragma unroll
    for (int i = 0; i < 8; i++)
        #pragma unroll
        for (int j = 0; j < 8; j++) acc[i][j] = 0.f;

    for (int k0 = 0; k0 < K; k0 += GBK) {
        float4 av = *reinterpret_cast<const float4*>(Aptr);
        Aptr += GBK;
        As[acol + 0][arow] = av.x;
        As[acol + 1][arow] = av.y;
        As[acol + 2][arow] = av.z;
        As[acol + 3][arow] = av.w;

        float4 bv = *reinterpret_cast<const float4*>(Bptr);
        Bptr += (size_t)GBK * N;
        *reinterpret_cast<float4*>(&Bs[brow][bcol]) = bv;

        __syncthreads();

        #pragma unroll
        for (int kk = 0; kk < GBK; kk++) {
            float af[8], bf[8];
            *reinterpret_cast<float4*>(&af[0]) =
                *reinterpret_cast<const float4*>(&As[kk][ty * 8]);
            *reinterpret_cast<float4*>(&af[4]) =
                *reinterpret_cast<const float4*>(&As[kk][ty * 8 + 4]);
            *reinterpret_cast<float4*>(&bf[0]) =
                *reinterpret_cast<const float4*>(&Bs[kk][tx * 8]);
            *reinterpret_cast<float4*>(&bf[4]) =
                *reinterpret_cast<const float4*>(&Bs[kk][tx * 8 + 4]);
            #pragma unroll
            for (int i = 0; i < 8; i++)
                #pragma unroll
                for (int j = 0; j < 8; j++)
                    acc[i][j] += af[i] * bf[j];
        }
        __syncthreads();
    }

    // Epilogue
    #pragma unroll
    for (int i = 0; i < 8; i++) {
        const size_t row = (size_t)(bm + ty * 8 + i) * N;
        #pragma unroll
        for (int jb = 0; jb < 2; jb++) {
            const int c = bn + tx * 8 + jb * 4;
            float4 o;
            o.x = acc[i][jb * 4 + 0];
            o.y = acc[i][jb * 4 + 1];
            o.z = acc[i][jb * 4 + 2];
            o.w = acc[i][jb * 4 + 3];
            if (bias) {
                o.x += bias[c + 0];
                o.y += bias[c + 1];
                o.z += bias[c + 2];
                o.w += bias[c + 3];
            }
            *reinterpret_cast<float4*>(&C[row + c]) = o;
        }
    }
}

// ---------------------------------------------------------------------------
// Flash attention (fp32, online softmax).
// One block = one (b,h) pair x one 64-row q tile. 256 threads.
// Thread (tq = tid/16, tk = tid%16) owns S/O rows tq*4..+3, cols {tk+16j}.
// smem strides of 65 floats keep strided column reads bank-conflict-free.
// ---------------------------------------------------------------------------
#define BQ  64
#define BKV 64
#define SS  65                       // smem row stride (floats)
#define ATTN_SMEM_FLOATS (4 * BQ * SS)
#define ATTN_SMEM_BYTES  (ATTN_SMEM_FLOATS * 4)

__global__ __launch_bounds__(256)
void attn_kernel(const float* __restrict__ Q, const float* __restrict__ K,
                 const float* __restrict__ V, float* __restrict__ O)
{
    extern __shared__ float sm[];
    float* Qs = sm;                    // [64][65]
    float* Ks = Qs + BQ * SS;          // [64][65]
    float* Vs = Ks + BKV * SS;         // [64][65]
    float* Ps = Vs + BKV * SS;         // [64][65]

    const int tid = threadIdx.x;
    const int tq  = tid >> 4;          // 0..15
    const int tk  = tid & 15;          // 0..15

    const int qt = (int)gridDim.x - 1 - (int)blockIdx.x;   // heavy tiles first
    const int bh = blockIdx.y;
    const int b  = bh >> 4;
    const int h  = bh & 15;

    const int rowbase = b * SEQ;
    const int colbase = h * HDIM;

    // ---- load Q tile (scaled by 1/sqrt(Dh)) ----
    #pragma unroll
    for (int r = 0; r < 4; r++) {
        int fi  = tid + r * 256;           // 0..1023 float4 units
        int row = fi >> 4;                 // 0..63
        int c4  = (fi & 15) << 2;          // 0,4,...,60
        float4 v = *reinterpret_cast<const float4*>(
            &Q[(size_t)(rowbase + qt * BQ + row) * DOUT + colbase + c4]);
        float* dst = &Qs[row * SS + c4];
        dst[0] = v.x * 0.125f; dst[1] = v.y * 0.125f;
        dst[2] = v.z * 0.125f; dst[3] = v.w * 0.125f;
    }

    float acc[4][4];
    float m_old[4], l_old[4];
    #pragma unroll
    for (int i = 0; i < 4; i++) {
        m_old[i] = -1e30f;
        l_old[i] = 0.f;
        #pragma unroll
        for (int j = 0; j < 4; j++) acc[i][j] = 0.f;
    }

    const int nkt = qt + 1;    // causal: k tiles 0..qt
    for (int kt = 0; kt < nkt; kt++) {
        __syncthreads();   // prev PV done (and Q load on first iter)

        // ---- load K,V tiles ----
        #pragma unroll
        for (int r = 0; r < 4; r++) {
            int fi  = tid + r * 256;
            int row = fi >> 4;
            int c4  = (fi & 15) << 2;
            size_t goff = (size_t)(rowbase + kt * BKV + row) * DOUT + colbase + c4;
            float4 kv4 = *reinterpret_cast<const float4*>(&K[goff]);
            float* kd = &Ks[row * SS + c4];
            kd[0] = kv4.x; kd[1] = kv4.y; kd[2] = kv4.z; kd[3] = kv4.w;
            float4 vv4 = *reinterpret_cast<const float4*>(&V[goff]);
            float* vd = &Vs[row * SS + c4];
            vd[0] = vv4.x; vd[1] = vv4.y; vd[2] = vv4.z; vd[3] = vv4.w;
        }
        __syncthreads();

        // ---- S = Qs . Ks^T ----
        float s[4][4];
        #pragma unroll
        for (int i = 0; i < 4; i++)
            #pragma unroll
            for (int j = 0; j < 4; j++) s[i][j] = 0.f;

        #pragma unroll 8
        for (int d = 0; d < HDIM; d++) {
            float q0 = Qs[(tq * 4 + 0) * SS + d];
            float q1 = Qs[(tq * 4 + 1) * SS + d];
            float q2 = Qs[(tq * 4 + 2) * SS + d];
            float q3 = Qs[(tq * 4 + 3) * SS + d];
            #pragma unroll
            for (int j = 0; j < 4; j++) {
                float kv = Ks[(tk + j * 16) * SS + d];
                s[0][j] += q0 * kv;
                s[1][j] += q1 * kv;
                s[2][j] += q2 * kv;
                s[3][j] += q3 * kv;
            }
        }

        // ---- causal mask (diagonal tile only) ----
        if (kt == qt) {
            #pragma unroll
            for (int i = 0; i < 4; i++) {
                int qg = tq * 4 + i;
                #pragma unroll
                for (int j = 0; j < 4; j++) {
                    int kg = tk + j * 16;
                    if (kg > qg) s[i][j] = -1e30f;
                }
            }
        }

        // ---- online softmax (rows reduced over the 16-lane half-warp) ----
        float alpha[4];
        #pragma unroll
        for (int i = 0; i < 4; i++) {
            float rmax = fmaxf(fmaxf(s[i][0], s[i][1]), fmaxf(s[i][2], s[i][3]));
            #pragma unroll
            for (int off = 8; off >= 1; off >>= 1)
                rmax = fmaxf(rmax, __shfl_xor_sync(0xffffffffu, rmax, off, 16));
            float mnew = fmaxf(m_old[i], rmax);
            alpha[i] = __expf(m_old[i] - mnew);
            float rsum = 0.f;
            #pragma unroll
            for (int j = 0; j < 4; j++) {
                float p = __expf(s[i][j] - mnew);
                s[i][j] = p;
                rsum += p;
            }
            #pragma unroll
            for (int off = 8; off >= 1; off >>= 1)
                rsum += __shfl_xor_sync(0xffffffffu, rsum, off, 16);
            l_old[i] = l_old[i] * alpha[i] + rsum;
            m_old[i] = mnew;
        }

        // ---- publish P, rescale O ----
        #pragma unroll
        for (int i = 0; i < 4; i++) {
            #pragma unroll
            for (int j = 0; j < 4; j++) {
                Ps[(tq * 4 + i) * SS + tk + j * 16] = s[i][j];
                acc[i][j] *= alpha[i];
            }
        }
        __syncthreads();

        // ---- O += P . V ----
        #pragma unroll 8
        for (int k = 0; k < BKV; k++) {
            float p0 = Ps[(tq * 4 + 0) * SS + k];
            float p1 = Ps[(tq * 4 + 1) * SS + k];
            float p2 = Ps[(tq * 4 + 2) * SS + k];
            float p3 = Ps[(tq * 4 + 3) * SS + k];
            #pragma unroll
            for (int j = 0; j < 4; j++) {
                float vv = Vs[k * SS + tk + j * 16];
                acc[0][j] += p0 * vv;
                acc[1][j] += p1 * vv;
                acc[2][j] += p2 * vv;
                acc[3][j] += p3 * vv;
            }
        }
    }

    // ---- epilogue: O /= l ----
    #pragma unroll
    for (int i = 0; i < 4; i++) {
        float inv = 1.f / l_old[i];
        size_t row = (size_t)(rowbase + qt * BQ + tq * 4 + i) * DOUT;
        #pragma unroll
        for (int j = 0; j < 4; j++)
            O[row + colbase + tk + j * 16] = acc[i][j] * inv;
    }
}

// ---------------------------------------------------------------------------
// Launcher
// ---------------------------------------------------------------------------
extern "C" void kernel_launch(void* const* d_in, const int* in_sizes, int n_in,
                              void* d_out, int out_size)
{
    const float* x  = (const float*)d_in[0];
    const float* Wq = (const float*)d_in[1];
    const float* Wk = (const float*)d_in[2];
    const float* Wv = (const float*)d_in[3];
    const float* Wo = (const float*)d_in[4];
    const float* bo = (const float*)d_in[5];
    float* out = (float*)d_out;

    float* Qp;  cudaGetSymbolAddress((void**)&Qp,  g_Q);
    float* Kp;  cudaGetSymbolAddress((void**)&Kp,  g_K);
    float* Vp;  cudaGetSymbolAddress((void**)&Vp,  g_V);
    float* Cp;  cudaGetSymbolAddress((void**)&Cp,  g_CTX);

    dim3 gemm_grid(DOUT / GBN, MROWS / GBM);   // (8, 32)
    sgemm_kernel<<<gemm_grid, 256>>>(x, Wq, nullptr, Qp, MROWS, DOUT, DIN);
    sgemm_kernel<<<gemm_grid, 256>>>(x, Wk, nullptr, Kp, MROWS, DOUT, DIN);
    sgemm_kernel<<<gemm_grid, 256>>>(x, Wv, nullptr, Vp, MROWS, DOUT, DIN);

    cudaFuncSetAttribute(attn_kernel,
                         cudaFuncAttributeMaxDynamicSharedMemorySize,
                         ATTN_SMEM_BYTES);
    dim3 attn_grid(SEQ / BQ, BATCH * NHEADS);  // (32, 32)
    attn_kernel<<<attn_grid, 256, ATTN_SMEM_BYTES>>>(Qp, Kp, Vp, Cp);

    sgemm_kernel<<<gemm_grid, 256>>>(Cp, Wo, bo, out, MROWS, DOUT, DOUT);
}

// round 9
// speedup vs baseline: 1.4354x; 1.4354x over previous
#include <cuda_runtime.h>
#include <cuda_bf16.h>
#include <cstdint>

// Problem constants
#define BATCH   2
#define SEQ     2048
#define DIN     1024
#define DOUT    1024
#define NHEADS  16
#define HDIM    64
#define MROWS   (BATCH * SEQ)        // 4096
#define WELEM   (DIN * DOUT)         // 1M

// ---------------------------------------------------------------------------
// Scratch (device globals — no runtime allocation allowed)
// ---------------------------------------------------------------------------
__device__ float g_Q[MROWS * DOUT];
__device__ float g_K[MROWS * DOUT];
__device__ float g_V[MROWS * DOUT];
__device__ float g_CTX[MROWS * DOUT];
__device__ __nv_bfloat16 g_xh[MROWS * DIN];
__device__ __nv_bfloat16 g_xl[MROWS * DIN];
__device__ __nv_bfloat16 g_ctxh[MROWS * DOUT];
__device__ __nv_bfloat16 g_ctxl[MROWS * DOUT];
__device__ __nv_bfloat16 g_Wth[4 * WELEM];   // transposed weights [N,K], hi
__device__ __nv_bfloat16 g_Wtl[4 * WELEM];   // transposed weights [N,K], lo

// ---------------------------------------------------------------------------
// Warp-MMA helpers (baseline PTX ISA, no arch-"a" features)
// ---------------------------------------------------------------------------
__device__ __forceinline__ uint32_t smem_u32(const void* p) {
    uint32_t a;
    asm("{ .reg .u64 t; cvta.to.shared.u64 t, %1; cvt.u32.u64 %0, t; }"
        : "=r"(a) : "l"(p));
    return a;
}

__device__ __forceinline__ void ldsm4(uint32_t* r, uint32_t addr) {
    asm volatile("ldmatrix.sync.aligned.m8n8.x4.shared.b16 {%0,%1,%2,%3}, [%4];"
                 : "=r"(r[0]), "=r"(r[1]), "=r"(r[2]), "=r"(r[3]) : "r"(addr));
}

__device__ __forceinline__ void mma_bf16(float* c, const uint32_t* a,
                                         uint32_t b0, uint32_t b1) {
    asm volatile(
        "mma.sync.aligned.m16n8k16.row.col.f32.bf16.bf16.f32 "
        "{%0,%1,%2,%3}, {%4,%5,%6,%7}, {%8,%9}, {%0,%1,%2,%3};"
        : "+f"(c[0]), "+f"(c[1]), "+f"(c[2]), "+f"(c[3])
        : "r"(a[0]), "r"(a[1]), "r"(a[2]), "r"(a[3]), "r"(b0), "r"(b1));
}

// ---------------------------------------------------------------------------
// Split fp32 -> (hi, lo) bf16
// ---------------------------------------------------------------------------
__global__ __launch_bounds__(256)
void split_kernel(const float* __restrict__ in, __nv_bfloat16* __restrict__ hi,
                  __nv_bfloat16* __restrict__ lo, int n4)
{
    int i = blockIdx.x * blockDim.x + threadIdx.x;
    if (i >= n4) return;
    float4 v = reinterpret_cast<const float4*>(in)[i];
    float f[4] = {v.x, v.y, v.z, v.w};
    __nv_bfloat16 h[4], l[4];
    #pragma unroll
    for (int k = 0; k < 4; k++) {
        h[k] = __float2bfloat16(f[k]);
        l[k] = __float2bfloat16(f[k] - __bfloat162float(h[k]));
    }
    __nv_bfloat162* hp = reinterpret_cast<__nv_bfloat162*>(hi) + i * 2;
    __nv_bfloat162* lp = reinterpret_cast<__nv_bfloat162*>(lo) + i * 2;
    hp[0] = __nv_bfloat162(h[0], h[1]);
    hp[1] = __nv_bfloat162(h[2], h[3]);
    lp[0] = __nv_bfloat162(l[0], l[1]);
    lp[1] = __nv_bfloat162(l[2], l[3]);
}

// ---------------------------------------------------------------------------
// Transpose + split: W [K,N] fp32 row-major -> Wt [N,K] bf16 hi/lo
// ---------------------------------------------------------------------------
__global__ __launch_bounds__(256)
void transpose_split_kernel(const float* __restrict__ W,
                            __nv_bfloat16* __restrict__ Th,
                            __nv_bfloat16* __restrict__ Tl)
{
    __shared__ float t[32][33];
    int bx = blockIdx.x * 32;   // N
    int by = blockIdx.y * 32;   // K
    int x = threadIdx.x, y = threadIdx.y;
    #pragma unroll
    for (int j = 0; j < 32; j += 8)
        t[y + j][x] = W[(size_t)(by + y + j) * DOUT + bx + x];
    __syncthreads();
    #pragma unroll
    for (int j = 0; j < 32; j += 8) {
        float v = t[x][y + j];
        __nv_bfloat16 h = __float2bfloat16(v);
        __nv_bfloat16 l = __float2bfloat16(v - __bfloat162float(h));
        size_t o = (size_t)(bx + y + j) * DIN + by + x;
        Th[o] = h;
        Tl[o] = l;
    }
}

// ---------------------------------------------------------------------------
// HMMA GEMM: C[4096,1024] = A[4096,1024] @ Wt[1024,1024]^T (+bias)
// A, Wt given as split bf16 (hi, lo).  CTA tile 128x128, K-tile 32.
// 8 warps in 2x4 (M x N); each warp computes 64x32 via m16n8k16 MMAs.
// Split accumulation: acc += Ah*Bh + Al*Bh + Ah*Bl  (3 MMAs per tile).
// ---------------------------------------------------------------------------
#define CTM 128
#define CTN 128
#define CTK 32
#define KPAD 40                         // bf16 row stride (80B: ldmatrix bank-safe)
#define GKIT (DIN / CTK)                // 32

__global__ __launch_bounds__(256, 1)
void mma_gemm(const __nv_bfloat16* __restrict__ Ah, const __nv_bfloat16* __restrict__ Al,
              const __nv_bfloat16* __restrict__ Bh, const __nv_bfloat16* __restrict__ Bl,
              const float* __restrict__ bias, float* __restrict__ C)
{
    __shared__ __align__(16) __nv_bfloat16 sAh[CTM * KPAD];
    __shared__ __align__(16) __nv_bfloat16 sAl[CTM * KPAD];
    __shared__ __align__(16) __nv_bfloat16 sBh[CTN * KPAD];
    __shared__ __align__(16) __nv_bfloat16 sBl[CTN * KPAD];

    const int tid  = threadIdx.x;
    const int w    = tid >> 5;
    const int lane = tid & 31;
    const int wm   = w >> 2;            // 0..1 (M)
    const int wn   = w & 3;             // 0..3 (N)
    const int bm   = blockIdx.y * CTM;
    const int bn   = blockIdx.x * CTN;

    // loader indices: row = u>>2, seg = u&3 (4 x uint4 segments per 32-elem row)
    const int lrow0 = tid >> 2;
    const int lseg  = tid & 3;

    // ldmatrix source addresses (per-thread row within the 16-row block,
    // k-half selected by lane>>4)
    const int arow = wm * 64 + (lane & 15);
    const int brow = wn * 32 + (lane & 15);
    const int khalf = (lane >> 4) * 8;
    const uint32_t uAh = smem_u32(sAh), uAl = smem_u32(sAl);
    const uint32_t uBh = smem_u32(sBh), uBl = smem_u32(sBl);

    float acc[4][4][4];
    #pragma unroll
    for (int mt = 0; mt < 4; mt++)
        #pragma unroll
        for (int nt = 0; nt < 4; nt++)
            #pragma unroll
            for (int e = 0; e < 4; e++) acc[mt][nt][e] = 0.f;

    uint4 rAh[2], rAl[2], rBh[2], rBl[2];

    #define GLOAD(g, grow0, k0, r) do {                                        \
        _Pragma("unroll")                                                      \
        for (int t = 0; t < 2; t++) {                                          \
            int row = lrow0 + t * 64;                                          \
            (r)[t] = *reinterpret_cast<const uint4*>(                          \
                (g) + (size_t)((grow0) + row) * 1024 + (k0) + lseg * 8);       \
        }                                                                      \
    } while (0)
    #define STS(r, s) do {                                                     \
        _Pragma("unroll")                                                      \
        for (int t = 0; t < 2; t++) {                                          \
            int row = lrow0 + t * 64;                                          \
            *reinterpret_cast<uint4*>((s) + row * KPAD + lseg * 8) = (r)[t];   \
        }                                                                      \
    } while (0)

    GLOAD(Ah, bm, 0, rAh); GLOAD(Al, bm, 0, rAl);
    GLOAD(Bh, bn, 0, rBh); GLOAD(Bl, bn, 0, rBl);
    STS(rAh, sAh); STS(rAl, sAl); STS(rBh, sBh); STS(rBl, sBl);

    for (int it = 0; it < GKIT; it++) {
        __syncthreads();

        if (it + 1 < GKIT) {
            const int k0 = (it + 1) * CTK;
            GLOAD(Ah, bm, k0, rAh); GLOAD(Al, bm, k0, rAl);
            GLOAD(Bh, bn, k0, rBh); GLOAD(Bl, bn, k0, rBl);
        }

        #pragma unroll
        for (int ks = 0; ks < 2; ks++) {
            const int kb = ks * 16 + khalf;
            uint32_t bh[8], bl[8];
            ldsm4(bh + 0, uBh + ((brow +  0) * KPAD + kb) * 2);
            ldsm4(bh + 4, uBh + ((brow + 16) * KPAD + kb) * 2);
            ldsm4(bl + 0, uBl + ((brow +  0) * KPAD + kb) * 2);
            ldsm4(bl + 4, uBl + ((brow + 16) * KPAD + kb) * 2);

            #pragma unroll
            for (int mt = 0; mt < 4; mt++) {
                uint32_t ah[4], al[4];
                ldsm4(ah, uAh + ((arow + mt * 16) * KPAD + kb) * 2);
                ldsm4(al, uAl + ((arow + mt * 16) * KPAD + kb) * 2);
                #pragma unroll
                for (int nt = 0; nt < 4; nt++) {
                    const int i0 = 4 * (nt >> 1) + (nt & 1);
                    mma_bf16(acc[mt][nt], ah, bh[i0], bh[i0 + 2]);
                    mma_bf16(acc[mt][nt], al, bh[i0], bh[i0 + 2]);
                    mma_bf16(acc[mt][nt], ah, bl[i0], bl[i0 + 2]);
                }
            }
        }

        __syncthreads();
        if (it + 1 < GKIT) {
            STS(rAh, sAh); STS(rAl, sAl); STS(rBh, sBh); STS(rBl, sBl);
        }
    }

    // epilogue: fragment (m16n8) -> thread holds c0,c1 @ (r, 2c), c2,c3 @ (r+8, 2c)
    const int erow = bm + wm * 64 + (lane >> 2);
    #pragma unroll
    for (int nt = 0; nt < 4; nt++) {
        const int col = bn + wn * 32 + nt * 8 + (lane & 3) * 2;
        float bx = 0.f, by = 0.f;
        if (bias) { bx = bias[col]; by = bias[col + 1]; }
        #pragma unroll
        for (int mt = 0; mt < 4; mt++) {
            const int r0 = erow + mt * 16;
            float2 v0 = make_float2(acc[mt][nt][0] + bx, acc[mt][nt][1] + by);
            float2 v1 = make_float2(acc[mt][nt][2] + bx, acc[mt][nt][3] + by);
            *reinterpret_cast<float2*>(C + (size_t)r0 * DOUT + col) = v0;
            *reinterpret_cast<float2*>(C + (size_t)(r0 + 8) * DOUT + col) = v1;
        }
    }
    #undef GLOAD
    #undef STS
}

// ---------------------------------------------------------------------------
// Flash attention (fp32, online softmax) — unchanged (640us)
// ---------------------------------------------------------------------------
#define BQ  64
#define BKV 64
#define SS  65
#define ATTN_SMEM_FLOATS (4 * BQ * SS)
#define ATTN_SMEM_BYTES  (ATTN_SMEM_FLOATS * 4)

__global__ __launch_bounds__(256)
void attn_kernel(const float* __restrict__ Q, const float* __restrict__ K,
                 const float* __restrict__ V, float* __restrict__ O)
{
    extern __shared__ float smf[];
    float* Qs = smf;
    float* Ks = Qs + BQ * SS;
    float* Vs = Ks + BKV * SS;
    float* Ps = Vs + BKV * SS;

    const int tid = threadIdx.x;
    const int tq  = tid >> 4;
    const int tk  = tid & 15;

    const int qt = (int)gridDim.x - 1 - (int)blockIdx.x;
    const int bh = blockIdx.y;
    const int b  = bh >> 4;
    const int h  = bh & 15;

    const int rowbase = b * SEQ;
    const int colbase = h * HDIM;

    #pragma unroll
    for (int r = 0; r < 4; r++) {
        int fi  = tid + r * 256;
        int row = fi >> 4;
        int c4  = (fi & 15) << 2;
        float4 v = *reinterpret_cast<const float4*>(
            &Q[(size_t)(rowbase + qt * BQ + row) * DOUT + colbase + c4]);
        float* dst = &Qs[row * SS + c4];
        dst[0] = v.x * 0.125f; dst[1] = v.y * 0.125f;
        dst[2] = v.z * 0.125f; dst[3] = v.w * 0.125f;
    }

    float acc[4][4];
    float m_old[4], l_old[4];
    #pragma unroll
    for (int i = 0; i < 4; i++) {
        m_old[i] = -1e30f;
        l_old[i] = 0.f;
        #pragma unroll
        for (int j = 0; j < 4; j++) acc[i][j] = 0.f;
    }

    const int nkt = qt + 1;
    for (int kt = 0; kt < nkt; kt++) {
        __syncthreads();

        #pragma unroll
        for (int r = 0; r < 4; r++) {
            int fi  = tid + r * 256;
            int row = fi >> 4;
            int c4  = (fi & 15) << 2;
            size_t goff = (size_t)(rowbase + kt * BKV + row) * DOUT + colbase + c4;
            float4 kv4 = *reinterpret_cast<const float4*>(&K[goff]);
            float* kd = &Ks[row * SS + c4];
            kd[0] = kv4.x; kd[1] = kv4.y; kd[2] = kv4.z; kd[3] = kv4.w;
            float4 vv4 = *reinterpret_cast<const float4*>(&V[goff]);
            float* vd = &Vs[row * SS + c4];
            vd[0] = vv4.x; vd[1] = vv4.y; vd[2] = vv4.z; vd[3] = vv4.w;
        }
        __syncthreads();

        float s[4][4];
        #pragma unroll
        for (int i = 0; i < 4; i++)
            #pragma unroll
            for (int j = 0; j < 4; j++) s[i][j] = 0.f;

        #pragma unroll 8
        for (int d = 0; d < HDIM; d++) {
            float q0 = Qs[(tq * 4 + 0) * SS + d];
            float q1 = Qs[(tq * 4 + 1) * SS + d];
            float q2 = Qs[(tq * 4 + 2) * SS + d];
            float q3 = Qs[(tq * 4 + 3) * SS + d];
            #pragma unroll
            for (int j = 0; j < 4; j++) {
                float kv = Ks[(tk + j * 16) * SS + d];
                s[0][j] += q0 * kv;
                s[1][j] += q1 * kv;
                s[2][j] += q2 * kv;
                s[3][j] += q3 * kv;
            }
        }

        if (kt == qt) {
            #pragma unroll
            for (int i = 0; i < 4; i++) {
                int qg = tq * 4 + i;
                #pragma unroll
                for (int j = 0; j < 4; j++) {
                    int kg = tk + j * 16;
                    if (kg > qg) s[i][j] = -1e30f;
                }
            }
        }

        float alpha[4];
        #pragma unroll
        for (int i = 0; i < 4; i++) {
            float rmax = fmaxf(fmaxf(s[i][0], s[i][1]), fmaxf(s[i][2], s[i][3]));
            #pragma unroll
            for (int off = 8; off >= 1; off >>= 1)
                rmax = fmaxf(rmax, __shfl_xor_sync(0xffffffffu, rmax, off, 16));
            float mnew = fmaxf(m_old[i], rmax);
            alpha[i] = __expf(m_old[i] - mnew);
            float rsum = 0.f;
            #pragma unroll
            for (int j = 0; j < 4; j++) {
                float p = __expf(s[i][j] - mnew);
                s[i][j] = p;
                rsum += p;
            }
            #pragma unroll
            for (int off = 8; off >= 1; off >>= 1)
                rsum += __shfl_xor_sync(0xffffffffu, rsum, off, 16);
            l_old[i] = l_old[i] * alpha[i] + rsum;
            m_old[i] = mnew;
        }

        #pragma unroll
        for (int i = 0; i < 4; i++) {
            #pragma unroll
            for (int j = 0; j < 4; j++) {
                Ps[(tq * 4 + i) * SS + tk + j * 16] = s[i][j];
                acc[i][j] *= alpha[i];
            }
        }
        __syncthreads();

        #pragma unroll 8
        for (int k = 0; k < BKV; k++) {
            float p0 = Ps[(tq * 4 + 0) * SS + k];
            float p1 = Ps[(tq * 4 + 1) * SS + k];
            float p2 = Ps[(tq * 4 + 2) * SS + k];
            float p3 = Ps[(tq * 4 + 3) * SS + k];
            #pragma unroll
            for (int j = 0; j < 4; j++) {
                float vv = Vs[k * SS + tk + j * 16];
                acc[0][j] += p0 * vv;
                acc[1][j] += p1 * vv;
                acc[2][j] += p2 * vv;
                acc[3][j] += p3 * vv;
            }
        }
    }

    #pragma unroll
    for (int i = 0; i < 4; i++) {
        float inv = 1.f / l_old[i];
        size_t row = (size_t)(rowbase + qt * BQ + tq * 4 + i) * DOUT;
        #pragma unroll
        for (int j = 0; j < 4; j++)
            O[row + colbase + tk + j * 16] = acc[i][j] * inv;
    }
}

// ---------------------------------------------------------------------------
// Launcher
// ---------------------------------------------------------------------------
extern "C" void kernel_launch(void* const* d_in, const int* in_sizes, int n_in,
                              void* d_out, int out_size)
{
    const float* x  = (const float*)d_in[0];
    const float* Wq = (const float*)d_in[1];
    const float* Wk = (const float*)d_in[2];
    const float* Wv = (const float*)d_in[3];
    const float* Wo = (const float*)d_in[4];
    const float* bo = (const float*)d_in[5];
    float* out = (float*)d_out;

    float* Qp;  cudaGetSymbolAddress((void**)&Qp,  g_Q);
    float* Kp;  cudaGetSymbolAddress((void**)&Kp,  g_K);
    float* Vp;  cudaGetSymbolAddress((void**)&Vp,  g_V);
    float* Cp;  cudaGetSymbolAddress((void**)&Cp,  g_CTX);
    __nv_bfloat16 *xh, *xl, *ch, *cl, *Wth, *Wtl;
    cudaGetSymbolAddress((void**)&xh,  g_xh);
    cudaGetSymbolAddress((void**)&xl,  g_xl);
    cudaGetSymbolAddress((void**)&ch,  g_ctxh);
    cudaGetSymbolAddress((void**)&cl,  g_ctxl);
    cudaGetSymbolAddress((void**)&Wth, g_Wth);
    cudaGetSymbolAddress((void**)&Wtl, g_Wtl);

    const int n4 = MROWS * DIN / 4;   // 1,048,576

    // split x -> bf16 hi/lo
    split_kernel<<<(n4 + 255) / 256, 256>>>(x, xh, xl, n4);

    // transpose + split the four weight matrices
    dim3 tb(32, 8), tg(32, 32);
    transpose_split_kernel<<<tg, tb>>>(Wq, Wth + 0 * WELEM, Wtl + 0 * WELEM);
    transpose_split_kernel<<<tg, tb>>>(Wk, Wth + 1 * WELEM, Wtl + 1 * WELEM);
    transpose_split_kernel<<<tg, tb>>>(Wv, Wth + 2 * WELEM, Wtl + 2 * WELEM);
    transpose_split_kernel<<<tg, tb>>>(Wo, Wth + 3 * WELEM, Wtl + 3 * WELEM);

    // HMMA GEMMs for Q, K, V
    dim3 gg(DOUT / CTN, MROWS / CTM);   // (8, 32)
    mma_gemm<<<gg, 256>>>(xh, xl, Wth + 0 * WELEM, Wtl + 0 * WELEM, nullptr, Qp);
    mma_gemm<<<gg, 256>>>(xh, xl, Wth + 1 * WELEM, Wtl + 1 * WELEM, nullptr, Kp);
    mma_gemm<<<gg, 256>>>(xh, xl, Wth + 2 * WELEM, Wtl + 2 * WELEM, nullptr, Vp);

    // attention
    cudaFuncSetAttribute(attn_kernel, cudaFuncAttributeMaxDynamicSharedMemorySize,
                         ATTN_SMEM_BYTES);
    dim3 attn_grid(SEQ / BQ, BATCH * NHEADS);
    attn_kernel<<<attn_grid, 256, ATTN_SMEM_BYTES>>>(Qp, Kp, Vp, Cp);

    // split ctx, then output projection (with bias)
    split_kernel<<<(n4 + 255) / 256, 256>>>(Cp, ch, cl, n4);
    mma_gemm<<<gg, 256>>>(ch, cl, Wth + 3 * WELEM, Wtl + 3 * WELEM, bo, out);
}

// round 10
// speedup vs baseline: 2.4159x; 1.6830x over previous
#include <cuda_runtime.h>
#include <cuda_bf16.h>
#include <cuda_fp16.h>
#include <cstdint>

// Problem constants
#define BATCH   2
#define SEQ     2048
#define DIN     1024
#define DOUT    1024
#define NHEADS  16
#define HDIM    64
#define MROWS   (BATCH * SEQ)        // 4096
#define WELEM   (DIN * DOUT)         // 1M

// ---------------------------------------------------------------------------
// Scratch (device globals — no runtime allocation allowed)
// ---------------------------------------------------------------------------
__device__ float g_Q[MROWS * DOUT];
__device__ float g_K[MROWS * DOUT];
__device__ float g_V[MROWS * DOUT];
__device__ float g_CTX[MROWS * DOUT];
__device__ __nv_bfloat16 g_xh[MROWS * DIN];
__device__ __nv_bfloat16 g_xl[MROWS * DIN];
__device__ __nv_bfloat16 g_ctxh[MROWS * DOUT];
__device__ __nv_bfloat16 g_ctxl[MROWS * DOUT];
__device__ __nv_bfloat16 g_Wth[4 * WELEM];   // transposed weights [N,K], hi
__device__ __nv_bfloat16 g_Wtl[4 * WELEM];   // transposed weights [N,K], lo
// fp16 split copies of Q/K/V for HMMA attention
__device__ __half g_Qh[MROWS * DOUT];
__device__ __half g_Ql[MROWS * DOUT];
__device__ __half g_Kh[MROWS * DOUT];
__device__ __half g_Kl[MROWS * DOUT];
__device__ __half g_Vh[MROWS * DOUT];
__device__ __half g_Vl[MROWS * DOUT];

// ---------------------------------------------------------------------------
// Warp-MMA helpers (baseline PTX ISA, no arch-"a" features)
// ---------------------------------------------------------------------------
__device__ __forceinline__ uint32_t smem_u32(const void* p) {
    uint32_t a;
    asm("{ .reg .u64 t; cvta.to.shared.u64 t, %1; cvt.u32.u64 %0, t; }"
        : "=r"(a) : "l"(p));
    return a;
}

__device__ __forceinline__ void ldsm4(uint32_t* r, uint32_t addr) {
    asm volatile("ldmatrix.sync.aligned.m8n8.x4.shared.b16 {%0,%1,%2,%3}, [%4];"
                 : "=r"(r[0]), "=r"(r[1]), "=r"(r[2]), "=r"(r[3]) : "r"(addr));
}
__device__ __forceinline__ void ldsm4t(uint32_t* r, uint32_t addr) {
    asm volatile("ldmatrix.sync.aligned.m8n8.x4.trans.shared.b16 {%0,%1,%2,%3}, [%4];"
                 : "=r"(r[0]), "=r"(r[1]), "=r"(r[2]), "=r"(r[3]) : "r"(addr));
}

__device__ __forceinline__ void mma_bf16(float* c, const uint32_t* a,
                                         uint32_t b0, uint32_t b1) {
    asm volatile(
        "mma.sync.aligned.m16n8k16.row.col.f32.bf16.bf16.f32 "
        "{%0,%1,%2,%3}, {%4,%5,%6,%7}, {%8,%9}, {%0,%1,%2,%3};"
        : "+f"(c[0]), "+f"(c[1]), "+f"(c[2]), "+f"(c[3])
        : "r"(a[0]), "r"(a[1]), "r"(a[2]), "r"(a[3]), "r"(b0), "r"(b1));
}
__device__ __forceinline__ void mma_f16(float* c, const uint32_t* a,
                                        uint32_t b0, uint32_t b1) {
    asm volatile(
        "mma.sync.aligned.m16n8k16.row.col.f32.f16.f16.f32 "
        "{%0,%1,%2,%3}, {%4,%5,%6,%7}, {%8,%9}, {%0,%1,%2,%3};"
        : "+f"(c[0]), "+f"(c[1]), "+f"(c[2]), "+f"(c[3])
        : "r"(a[0]), "r"(a[1]), "r"(a[2]), "r"(a[3]), "r"(b0), "r"(b1));
}

__device__ __forceinline__ uint32_t pack_h2(__half a, __half b) {
    __half2 h = __halves2half2(a, b);
    return *reinterpret_cast<uint32_t*>(&h);
}

// ---------------------------------------------------------------------------
// Split fp32 -> (hi, lo) bf16
// ---------------------------------------------------------------------------
__global__ __launch_bounds__(256)
void split_kernel(const float* __restrict__ in, __nv_bfloat16* __restrict__ hi,
                  __nv_bfloat16* __restrict__ lo, int n4)
{
    int i = blockIdx.x * blockDim.x + threadIdx.x;
    if (i >= n4) return;
    float4 v = reinterpret_cast<const float4*>(in)[i];
    float f[4] = {v.x, v.y, v.z, v.w};
    __nv_bfloat16 h[4], l[4];
    #pragma unroll
    for (int k = 0; k < 4; k++) {
        h[k] = __float2bfloat16(f[k]);
        l[k] = __float2bfloat16(f[k] - __bfloat162float(h[k]));
    }
    __nv_bfloat162* hp = reinterpret_cast<__nv_bfloat162*>(hi) + i * 2;
    __nv_bfloat162* lp = reinterpret_cast<__nv_bfloat162*>(lo) + i * 2;
    hp[0] = __nv_bfloat162(h[0], h[1]);
    hp[1] = __nv_bfloat162(h[2], h[3]);
    lp[0] = __nv_bfloat162(l[0], l[1]);
    lp[1] = __nv_bfloat162(l[2], l[3]);
}

// Split fp32 -> (hi, lo) fp16, with scale folded in
__global__ __launch_bounds__(256)
void split_half_kernel(const float* __restrict__ in, __half* __restrict__ hi,
                       __half* __restrict__ lo, float scale, int n4)
{
    int i = blockIdx.x * blockDim.x + threadIdx.x;
    if (i >= n4) return;
    float4 v = reinterpret_cast<const float4*>(in)[i];
    float f[4] = {v.x * scale, v.y * scale, v.z * scale, v.w * scale};
    __half h[4], l[4];
    #pragma unroll
    for (int k = 0; k < 4; k++) {
        h[k] = __float2half_rn(f[k]);
        l[k] = __float2half_rn(f[k] - __half2float(h[k]));
    }
    uint2 hp = make_uint2(pack_h2(h[0], h[1]), pack_h2(h[2], h[3]));
    uint2 lp = make_uint2(pack_h2(l[0], l[1]), pack_h2(l[2], l[3]));
    reinterpret_cast<uint2*>(hi)[i] = hp;
    reinterpret_cast<uint2*>(lo)[i] = lp;
}

// ---------------------------------------------------------------------------
// Transpose + split: W [K,N] fp32 row-major -> Wt [N,K] bf16 hi/lo
// ---------------------------------------------------------------------------
__global__ __launch_bounds__(256)
void transpose_split_kernel(const float* __restrict__ W,
                            __nv_bfloat16* __restrict__ Th,
                            __nv_bfloat16* __restrict__ Tl)
{
    __shared__ float t[32][33];
    int bx = blockIdx.x * 32;   // N
    int by = blockIdx.y * 32;   // K
    int x = threadIdx.x, y = threadIdx.y;
    #pragma unroll
    for (int j = 0; j < 32; j += 8)
        t[y + j][x] = W[(size_t)(by + y + j) * DOUT + bx + x];
    __syncthreads();
    #pragma unroll
    for (int j = 0; j < 32; j += 8) {
        float v = t[x][y + j];
        __nv_bfloat16 h = __float2bfloat16(v);
        __nv_bfloat16 l = __float2bfloat16(v - __bfloat162float(h));
        size_t o = (size_t)(bx + y + j) * DIN + by + x;
        Th[o] = h;
        Tl[o] = l;
    }
}

// ---------------------------------------------------------------------------
// HMMA GEMM (unchanged from R9): C = A @ Wt^T (+bias), split bf16, 128x128x32
// ---------------------------------------------------------------------------
#define CTM 128
#define CTN 128
#define CTK 32
#define KPAD 40
#define GKIT (DIN / CTK)

__global__ __launch_bounds__(256, 1)
void mma_gemm(const __nv_bfloat16* __restrict__ Ah, const __nv_bfloat16* __restrict__ Al,
              const __nv_bfloat16* __restrict__ Bh, const __nv_bfloat16* __restrict__ Bl,
              const float* __restrict__ bias, float* __restrict__ C)
{
    __shared__ __align__(16) __nv_bfloat16 sAh[CTM * KPAD];
    __shared__ __align__(16) __nv_bfloat16 sAl[CTM * KPAD];
    __shared__ __align__(16) __nv_bfloat16 sBh[CTN * KPAD];
    __shared__ __align__(16) __nv_bfloat16 sBl[CTN * KPAD];

    const int tid  = threadIdx.x;
    const int w    = tid >> 5;
    const int lane = tid & 31;
    const int wm   = w >> 2;
    const int wn   = w & 3;
    const int bm   = blockIdx.y * CTM;
    const int bn   = blockIdx.x * CTN;

    const int lrow0 = tid >> 2;
    const int lseg  = tid & 3;

    const int arow = wm * 64 + (lane & 15);
    const int brow = wn * 32 + (lane & 15);
    const int khalf = (lane >> 4) * 8;
    const uint32_t uAh = smem_u32(sAh), uAl = smem_u32(sAl);
    const uint32_t uBh = smem_u32(sBh), uBl = smem_u32(sBl);

    float acc[4][4][4];
    #pragma unroll
    for (int mt = 0; mt < 4; mt++)
        #pragma unroll
        for (int nt = 0; nt < 4; nt++)
            #pragma unroll
            for (int e = 0; e < 4; e++) acc[mt][nt][e] = 0.f;

    uint4 rAh[2], rAl[2], rBh[2], rBl[2];

    #define GLOAD(g, grow0, k0, r) do {                                        \
        _Pragma("unroll")                                                      \
        for (int t = 0; t < 2; t++) {                                          \
            int row = lrow0 + t * 64;                                          \
            (r)[t] = *reinterpret_cast<const uint4*>(                          \
                (g) + (size_t)((grow0) + row) * 1024 + (k0) + lseg * 8);       \
        }                                                                      \
    } while (0)
    #define STSX(r, s) do {                                                    \
        _Pragma("unroll")                                                      \
        for (int t = 0; t < 2; t++) {                                          \
            int row = lrow0 + t * 64;                                          \
            *reinterpret_cast<uint4*>((s) + row * KPAD + lseg * 8) = (r)[t];   \
        }                                                                      \
    } while (0)

    GLOAD(Ah, bm, 0, rAh); GLOAD(Al, bm, 0, rAl);
    GLOAD(Bh, bn, 0, rBh); GLOAD(Bl, bn, 0, rBl);
    STSX(rAh, sAh); STSX(rAl, sAl); STSX(rBh, sBh); STSX(rBl, sBl);

    for (int it = 0; it < GKIT; it++) {
        __syncthreads();

        if (it + 1 < GKIT) {
            const int k0 = (it + 1) * CTK;
            GLOAD(Ah, bm, k0, rAh); GLOAD(Al, bm, k0, rAl);
            GLOAD(Bh, bn, k0, rBh); GLOAD(Bl, bn, k0, rBl);
        }

        #pragma unroll
        for (int ks = 0; ks < 2; ks++) {
            const int kb = ks * 16 + khalf;
            uint32_t bh[8], bl[8];
            ldsm4(bh + 0, uBh + ((brow +  0) * KPAD + kb) * 2);
            ldsm4(bh + 4, uBh + ((brow + 16) * KPAD + kb) * 2);
            ldsm4(bl + 0, uBl + ((brow +  0) * KPAD + kb) * 2);
            ldsm4(bl + 4, uBl + ((brow + 16) * KPAD + kb) * 2);

            #pragma unroll
            for (int mt = 0; mt < 4; mt++) {
                uint32_t ah[4], al[4];
                ldsm4(ah, uAh + ((arow + mt * 16) * KPAD + kb) * 2);
                ldsm4(al, uAl + ((arow + mt * 16) * KPAD + kb) * 2);
                #pragma unroll
                for (int nt = 0; nt < 4; nt++) {
                    const int i0 = 4 * (nt >> 1) + (nt & 1);
                    mma_bf16(acc[mt][nt], ah, bh[i0], bh[i0 + 2]);
                    mma_bf16(acc[mt][nt], al, bh[i0], bh[i0 + 2]);
                    mma_bf16(acc[mt][nt], ah, bl[i0], bl[i0 + 2]);
                }
            }
        }

        __syncthreads();
        if (it + 1 < GKIT) {
            STSX(rAh, sAh); STSX(rAl, sAl); STSX(rBh, sBh); STSX(rBl, sBl);
        }
    }

    const int erow = bm + wm * 64 + (lane >> 2);
    #pragma unroll
    for (int nt = 0; nt < 4; nt++) {
        const int col = bn + wn * 32 + nt * 8 + (lane & 3) * 2;
        float bx = 0.f, by = 0.f;
        if (bias) { bx = bias[col]; by = bias[col + 1]; }
        #pragma unroll
        for (int mt = 0; mt < 4; mt++) {
            const int r0 = erow + mt * 16;
            float2 v0 = make_float2(acc[mt][nt][0] + bx, acc[mt][nt][1] + by);
            float2 v1 = make_float2(acc[mt][nt][2] + bx, acc[mt][nt][3] + by);
            *reinterpret_cast<float2*>(C + (size_t)r0 * DOUT + col) = v0;
            *reinterpret_cast<float2*>(C + (size_t)(r0 + 8) * DOUT + col) = v1;
        }
    }
    #undef GLOAD
    #undef STSX
}

// ---------------------------------------------------------------------------
// HMMA flash attention. CTA = 128 q-rows x one (b,h). 8 warps x 16 q-rows.
// KV tiles of 64, split-fp16 3-MMA accumulation for both QK^T and PV.
// ---------------------------------------------------------------------------
#define ABQ 128
#define AKV 64
#define AST 72                          // smem row stride (halves)
#define KVT_H (AKV * AST)               // halves per tensor tile (4608)
#define STAGE_H (4 * KVT_H)             // halves per stage (18432)
#define ASMEM_B (2 * STAGE_H * 2)       // 73728 bytes

__global__ __launch_bounds__(256, 1)
void attn_mma(const __half* __restrict__ Qh, const __half* __restrict__ Ql,
              const __half* __restrict__ Kh, const __half* __restrict__ Kl,
              const __half* __restrict__ Vh, const __half* __restrict__ Vl,
              float* __restrict__ O)
{
    extern __shared__ __align__(16) __half s[];
    const uint32_t sbase = smem_u32(s);

    const int tid  = threadIdx.x;
    const int w    = tid >> 5;
    const int lane = tid & 31;

    const int qt = (int)gridDim.x - 1 - (int)blockIdx.x;   // heavy first
    const int bh = blockIdx.y;
    const int b  = bh >> 4;
    const int h  = bh & 15;

    const size_t rowbase = (size_t)b * SEQ;
    const int    colbase = h * HDIM;
    const int    qbase   = qt * ABQ;            // seq-local
    const int    wq      = qbase + w * 16;      // warp q base (seq-local)

    // ---- stage Q hi/lo into buffer region, load A fragments ----
    {
        #pragma unroll
        for (int t = 0; t < 4; t++) {
            int u = tid + t * 256;
            int row = u >> 3, seg = u & 7;
            uint4 vh4 = *reinterpret_cast<const uint4*>(
                Qh + (rowbase + qbase + row) * 1024 + colbase + seg * 8);
            uint4 vl4 = *reinterpret_cast<const uint4*>(
                Ql + (rowbase + qbase + row) * 1024 + colbase + seg * 8);
            *reinterpret_cast<uint4*>(s + row * AST + seg * 8) = vh4;
            *reinterpret_cast<uint4*>(s + ABQ * AST + row * AST + seg * 8) = vl4;
        }
    }
    __syncthreads();

    uint32_t qfh[4][4], qfl[4][4];
    {
        const int arow = w * 16 + (lane & 15);
        const int k8   = (lane >> 4) * 8;
        #pragma unroll
        for (int ks = 0; ks < 4; ks++) {
            ldsm4(qfh[ks], sbase + (arow * AST + ks * 16 + k8) * 2);
            ldsm4(qfl[ks], sbase + ((ABQ * AST) + arow * AST + ks * 16 + k8) * 2);
        }
    }
    __syncthreads();

    float ctx[8][4];
    #pragma unroll
    for (int nt = 0; nt < 8; nt++)
        #pragma unroll
        for (int e = 0; e < 4; e++) ctx[nt][e] = 0.f;
    float mrow[2] = {-1e30f, -1e30f};
    float lrow[2] = {0.f, 0.f};

    const int nkt = 2 * qt + 2;

    uint4 rg[8];
    #define AGLD(kt_) do {                                                     \
        const __half* gt0[4] = {Kh, Kl, Vh, Vl};                               \
        _Pragma("unroll")                                                      \
        for (int tn = 0; tn < 4; tn++)                                         \
            _Pragma("unroll")                                                  \
            for (int t = 0; t < 2; t++) {                                      \
                int u = tid + t * 256;                                         \
                int row = u >> 3, seg = u & 7;                                 \
                rg[tn * 2 + t] = *reinterpret_cast<const uint4*>(              \
                    gt0[tn] + (rowbase + (kt_) * AKV + row) * 1024             \
                            + colbase + seg * 8);                              \
            }                                                                  \
    } while (0)
    #define ASTS(buf_) do {                                                    \
        __half* sb = s + (buf_) * STAGE_H;                                     \
        _Pragma("unroll")                                                      \
        for (int tn = 0; tn < 4; tn++)                                         \
            _Pragma("unroll")                                                  \
            for (int t = 0; t < 2; t++) {                                      \
                int u = tid + t * 256;                                         \
                int row = u >> 3, seg = u & 7;                                 \
                *reinterpret_cast<uint4*>(sb + tn * KVT_H + row * AST          \
                                          + seg * 8) = rg[tn * 2 + t];         \
            }                                                                  \
    } while (0)

    AGLD(0);
    ASTS(0);
    __syncthreads();

    for (int kt = 0; kt < nkt; kt++) {
        const int buf = kt & 1;
        if (kt + 1 < nkt) AGLD(kt + 1);

        const bool skip = (kt * AKV) > (wq + 15);   // tile fully above diagonal
        if (!skip) {
            const uint32_t kh_b = sbase + (buf * STAGE_H + 0 * KVT_H) * 2;
            const uint32_t kl_b = sbase + (buf * STAGE_H + 1 * KVT_H) * 2;
            const uint32_t vh_b = sbase + (buf * STAGE_H + 2 * KVT_H) * 2;
            const uint32_t vl_b = sbase + (buf * STAGE_H + 3 * KVT_H) * 2;

            // ---- S = Q K^T (split, 3 MMAs) ----
            float sv[8][4];
            #pragma unroll
            for (int nt = 0; nt < 8; nt++)
                #pragma unroll
                for (int e = 0; e < 4; e++) sv[nt][e] = 0.f;

            const int brow = lane & 15;
            const int k8   = (lane >> 4) * 8;
            #pragma unroll
            for (int ks = 0; ks < 4; ks++) {
                #pragma unroll
                for (int np = 0; np < 4; np++) {
                    uint32_t kh4[4], kl4[4];
                    const uint32_t off = ((np * 16 + brow) * AST + ks * 16 + k8) * 2;
                    ldsm4(kh4, kh_b + off);
                    ldsm4(kl4, kl_b + off);
                    mma_f16(sv[2 * np],     qfh[ks], kh4[0], kh4[2]);
                    mma_f16(sv[2 * np],     qfl[ks], kh4[0], kh4[2]);
                    mma_f16(sv[2 * np],     qfh[ks], kl4[0], kl4[2]);
                    mma_f16(sv[2 * np + 1], qfh[ks], kh4[1], kh4[3]);
                    mma_f16(sv[2 * np + 1], qfl[ks], kh4[1], kh4[3]);
                    mma_f16(sv[2 * np + 1], qfh[ks], kl4[1], kl4[3]);
                }
            }

            // ---- causal mask (only tiles that touch the diagonal) ----
            if (kt * AKV + AKV - 1 > wq) {
                const int qr = wq + (lane >> 2);
                #pragma unroll
                for (int nt = 0; nt < 8; nt++) {
                    const int kg0 = kt * AKV + nt * 8 + (lane & 3) * 2;
                    #pragma unroll
                    for (int e = 0; e < 4; e++) {
                        const int qg = qr + ((e >> 1) << 3);
                        const int kg = kg0 + (e & 1);
                        if (kg > qg) sv[nt][e] = -1e30f;
                    }
                }
            }

            // ---- online softmax (rows r=lane>>2 and r+8) ----
            float alpha[2];
            #pragma unroll
            for (int rr = 0; rr < 2; rr++) {
                float rmax = -1e30f;
                #pragma unroll
                for (int nt = 0; nt < 8; nt++)
                    rmax = fmaxf(rmax, fmaxf(sv[nt][2 * rr], sv[nt][2 * rr + 1]));
                rmax = fmaxf(rmax, __shfl_xor_sync(0xffffffffu, rmax, 1));
                rmax = fmaxf(rmax, __shfl_xor_sync(0xffffffffu, rmax, 2));
                const float mnew = fmaxf(mrow[rr], rmax);
                alpha[rr] = __expf(mrow[rr] - mnew);
                float rsum = 0.f;
                #pragma unroll
                for (int nt = 0; nt < 8; nt++) {
                    float p0 = __expf(sv[nt][2 * rr]     - mnew);
                    float p1 = __expf(sv[nt][2 * rr + 1] - mnew);
                    sv[nt][2 * rr] = p0; sv[nt][2 * rr + 1] = p1;
                    rsum += p0 + p1;
                }
                rsum += __shfl_xor_sync(0xffffffffu, rsum, 1);
                rsum += __shfl_xor_sync(0xffffffffu, rsum, 2);
                lrow[rr] = lrow[rr] * alpha[rr] + rsum;
                mrow[rr] = mnew;
            }
            #pragma unroll
            for (int nt = 0; nt < 8; nt++) {
                ctx[nt][0] *= alpha[0]; ctx[nt][1] *= alpha[0];
                ctx[nt][2] *= alpha[1]; ctx[nt][3] *= alpha[1];
            }

            // ---- pack P fragments (fp16 hi/lo) ----
            uint32_t pah[4][4], pal[4][4];
            #pragma unroll
            for (int t = 0; t < 4; t++) {
                #pragma unroll
                for (int half2i = 0; half2i < 4; half2i++) {
                    const int nt = 2 * t + (half2i >> 1);
                    const int e0 = (half2i & 1) * 2;
                    const float a0 = sv[nt][e0], a1 = sv[nt][e0 + 1];
                    const __half h0 = __float2half_rn(a0);
                    const __half h1 = __float2half_rn(a1);
                    pah[t][half2i] = pack_h2(h0, h1);
                    pal[t][half2i] = pack_h2(
                        __float2half_rn(a0 - __half2float(h0)),
                        __float2half_rn(a1 - __half2float(h1)));
                }
            }

            // ---- ctx += P V (split, 3 MMAs, ldmatrix.trans on V) ----
            #pragma unroll
            for (int t = 0; t < 4; t++) {
                #pragma unroll
                for (int dp = 0; dp < 4; dp++) {
                    uint32_t vh4[4], vl4[4];
                    const uint32_t off =
                        ((t * 16 + (lane & 15)) * AST + dp * 16 + k8) * 2;
                    ldsm4t(vh4, vh_b + off);
                    ldsm4t(vl4, vl_b + off);
                    mma_f16(ctx[2 * dp],     pah[t], vh4[0], vh4[1]);
                    mma_f16(ctx[2 * dp],     pal[t], vh4[0], vh4[1]);
                    mma_f16(ctx[2 * dp],     pah[t], vl4[0], vl4[1]);
                    mma_f16(ctx[2 * dp + 1], pah[t], vh4[2], vh4[3]);
                    mma_f16(ctx[2 * dp + 1], pal[t], vh4[2], vh4[3]);
                    mma_f16(ctx[2 * dp + 1], pah[t], vl4[2], vl4[3]);
                }
            }
        }

        if (kt + 1 < nkt) ASTS(buf ^ 1);
        __syncthreads();
    }

    // ---- epilogue: ctx /= l ----
    #pragma unroll
    for (int rr = 0; rr < 2; rr++) {
        const float inv = 1.f / lrow[rr];
        const size_t row = rowbase + qbase + w * 16 + (lane >> 2) + rr * 8;
        #pragma unroll
        for (int nt = 0; nt < 8; nt++) {
            const int col = colbase + nt * 8 + (lane & 3) * 2;
            float2 v = make_float2(ctx[nt][2 * rr] * inv, ctx[nt][2 * rr + 1] * inv);
            *reinterpret_cast<float2*>(O + row * 1024 + col) = v;
        }
    }
    #undef AGLD
    #undef ASTS
}

// ---------------------------------------------------------------------------
// Launcher
// ---------------------------------------------------------------------------
extern "C" void kernel_launch(void* const* d_in, const int* in_sizes, int n_in,
                              void* d_out, int out_size)
{
    const float* x  = (const float*)d_in[0];
    const float* Wq = (const float*)d_in[1];
    const float* Wk = (const float*)d_in[2];
    const float* Wv = (const float*)d_in[3];
    const float* Wo = (const float*)d_in[4];
    const float* bo = (const float*)d_in[5];
    float* out = (float*)d_out;

    float* Qp;  cudaGetSymbolAddress((void**)&Qp,  g_Q);
    float* Kp;  cudaGetSymbolAddress((void**)&Kp,  g_K);
    float* Vp;  cudaGetSymbolAddress((void**)&Vp,  g_V);
    float* Cp;  cudaGetSymbolAddress((void**)&Cp,  g_CTX);
    __nv_bfloat16 *xh, *xl, *ch, *cl, *Wth, *Wtl;
    cudaGetSymbolAddress((void**)&xh,  g_xh);
    cudaGetSymbolAddress((void**)&xl,  g_xl);
    cudaGetSymbolAddress((void**)&ch,  g_ctxh);
    cudaGetSymbolAddress((void**)&cl,  g_ctxl);
    cudaGetSymbolAddress((void**)&Wth, g_Wth);
    cudaGetSymbolAddress((void**)&Wtl, g_Wtl);
    __half *qhh, *qhl, *khh, *khl, *vhh, *vhl;
    cudaGetSymbolAddress((void**)&qhh, g_Qh);
    cudaGetSymbolAddress((void**)&qhl, g_Ql);
    cudaGetSymbolAddress((void**)&khh, g_Kh);
    cudaGetSymbolAddress((void**)&khl, g_Kl);
    cudaGetSymbolAddress((void**)&vhh, g_Vh);
    cudaGetSymbolAddress((void**)&vhl, g_Vl);

    const int n4 = MROWS * DIN / 4;

    // split x -> bf16 hi/lo
    split_kernel<<<(n4 + 255) / 256, 256>>>(x, xh, xl, n4);

    // transpose + split the four weight matrices
    dim3 tb(32, 8), tg(32, 32);
    transpose_split_kernel<<<tg, tb>>>(Wq, Wth + 0 * WELEM, Wtl + 0 * WELEM);
    transpose_split_kernel<<<tg, tb>>>(Wk, Wth + 1 * WELEM, Wtl + 1 * WELEM);
    transpose_split_kernel<<<tg, tb>>>(Wv, Wth + 2 * WELEM, Wtl + 2 * WELEM);
    transpose_split_kernel<<<tg, tb>>>(Wo, Wth + 3 * WELEM, Wtl + 3 * WELEM);

    // HMMA GEMMs for Q, K, V
    dim3 gg(DOUT / CTN, MROWS / CTM);
    mma_gemm<<<gg, 256>>>(xh, xl, Wth + 0 * WELEM, Wtl + 0 * WELEM, nullptr, Qp);
    mma_gemm<<<gg, 256>>>(xh, xl, Wth + 1 * WELEM, Wtl + 1 * WELEM, nullptr, Kp);
    mma_gemm<<<gg, 256>>>(xh, xl, Wth + 2 * WELEM, Wtl + 2 * WELEM, nullptr, Vp);

    // split Q/K/V -> fp16 hi/lo (scale folded into Q)
    split_half_kernel<<<(n4 + 255) / 256, 256>>>(Qp, qhh, qhl, 0.125f, n4);
    split_half_kernel<<<(n4 + 255) / 256, 256>>>(Kp, khh, khl, 1.0f, n4);
    split_half_kernel<<<(n4 + 255) / 256, 256>>>(Vp, vhh, vhl, 1.0f, n4);

    // HMMA flash attention
    cudaFuncSetAttribute(attn_mma, cudaFuncAttributeMaxDynamicSharedMemorySize,
                         ASMEM_B);
    dim3 attn_grid(SEQ / ABQ, BATCH * NHEADS);   // (16, 32)
    attn_mma<<<attn_grid, 256, ASMEM_B>>>(qhh, qhl, khh, khl, vhh, vhl, Cp);

    // split ctx, then output projection (with bias)
    split_kernel<<<(n4 + 255) / 256, 256>>>(Cp, ch, cl, n4);
    mma_gemm<<<gg, 256>>>(ch, cl, Wth + 3 * WELEM, Wtl + 3 * WELEM, bo, out);
}

// round 11
// speedup vs baseline: 2.6310x; 1.0890x over previous
#include <cuda_runtime.h>
#include <cuda_bf16.h>
#include <cuda_fp16.h>
#include <cstdint>

// Problem constants
#define BATCH   2
#define SEQ     2048
#define DIN     1024
#define DOUT    1024
#define NHEADS  16
#define HDIM    64
#define MROWS   (BATCH * SEQ)        // 4096
#define WELEM   (DIN * DOUT)         // 1M

// ---------------------------------------------------------------------------
// Scratch (device globals — no runtime allocation allowed)
// ---------------------------------------------------------------------------
__device__ __nv_bfloat16 g_xh[MROWS * DIN];
__device__ __nv_bfloat16 g_xl[MROWS * DIN];
__device__ __nv_bfloat16 g_ctxh[MROWS * DOUT];
__device__ __nv_bfloat16 g_ctxl[MROWS * DOUT];
__device__ __nv_bfloat16 g_Wth[4 * WELEM];   // transposed weights [N,K], hi
__device__ __nv_bfloat16 g_Wtl[4 * WELEM];   // transposed weights [N,K], lo
// fp16 split Q/K/V (written directly by the fused QKV GEMM epilogue)
__device__ __half g_Qh[MROWS * DOUT];
__device__ __half g_Ql[MROWS * DOUT];
__device__ __half g_Kh[MROWS * DOUT];
__device__ __half g_Kl[MROWS * DOUT];
__device__ __half g_Vh[MROWS * DOUT];
__device__ __half g_Vl[MROWS * DOUT];

// ---------------------------------------------------------------------------
// Warp-MMA / async-copy helpers (baseline PTX ISA, no arch-"a" features)
// ---------------------------------------------------------------------------
__device__ __forceinline__ uint32_t smem_u32(const void* p) {
    uint32_t a;
    asm("{ .reg .u64 t; cvta.to.shared.u64 t, %1; cvt.u32.u64 %0, t; }"
        : "=r"(a) : "l"(p));
    return a;
}
__device__ __forceinline__ void ldsm4(uint32_t* r, uint32_t addr) {
    asm volatile("ldmatrix.sync.aligned.m8n8.x4.shared.b16 {%0,%1,%2,%3}, [%4];"
                 : "=r"(r[0]), "=r"(r[1]), "=r"(r[2]), "=r"(r[3]) : "r"(addr));
}
__device__ __forceinline__ void ldsm4t(uint32_t* r, uint32_t addr) {
    asm volatile("ldmatrix.sync.aligned.m8n8.x4.trans.shared.b16 {%0,%1,%2,%3}, [%4];"
                 : "=r"(r[0]), "=r"(r[1]), "=r"(r[2]), "=r"(r[3]) : "r"(addr));
}
__device__ __forceinline__ void mma_bf16(float* c, const uint32_t* a,
                                         uint32_t b0, uint32_t b1) {
    asm volatile(
        "mma.sync.aligned.m16n8k16.row.col.f32.bf16.bf16.f32 "
        "{%0,%1,%2,%3}, {%4,%5,%6,%7}, {%8,%9}, {%0,%1,%2,%3};"
        : "+f"(c[0]), "+f"(c[1]), "+f"(c[2]), "+f"(c[3])
        : "r"(a[0]), "r"(a[1]), "r"(a[2]), "r"(a[3]), "r"(b0), "r"(b1));
}
__device__ __forceinline__ void mma_f16(float* c, const uint32_t* a,
                                        uint32_t b0, uint32_t b1) {
    asm volatile(
        "mma.sync.aligned.m16n8k16.row.col.f32.f16.f16.f32 "
        "{%0,%1,%2,%3}, {%4,%5,%6,%7}, {%8,%9}, {%0,%1,%2,%3};"
        : "+f"(c[0]), "+f"(c[1]), "+f"(c[2]), "+f"(c[3])
        : "r"(a[0]), "r"(a[1]), "r"(a[2]), "r"(a[3]), "r"(b0), "r"(b1));
}
__device__ __forceinline__ void cp16(uint32_t dst, const void* src) {
    asm volatile("cp.async.cg.shared.global [%0], [%1], 16;"
                 :: "r"(dst), "l"(src));
}
#define CP_COMMIT() asm volatile("cp.async.commit_group;" ::: "memory")
#define CP_WAIT1()  asm volatile("cp.async.wait_group 1;" ::: "memory")
#define CP_WAIT0()  asm volatile("cp.async.wait_group 0;" ::: "memory")

__device__ __forceinline__ uint32_t pack_h2(__half a, __half b) {
    __half2 h = __halves2half2(a, b);
    return *reinterpret_cast<uint32_t*>(&h);
}

// ---------------------------------------------------------------------------
// Split fp32 -> (hi, lo) bf16
// ---------------------------------------------------------------------------
__global__ __launch_bounds__(256)
void split_kernel(const float* __restrict__ in, __nv_bfloat16* __restrict__ hi,
                  __nv_bfloat16* __restrict__ lo, int n4)
{
    int i = blockIdx.x * blockDim.x + threadIdx.x;
    if (i >= n4) return;
    float4 v = reinterpret_cast<const float4*>(in)[i];
    float f[4] = {v.x, v.y, v.z, v.w};
    __nv_bfloat16 h[4], l[4];
    #pragma unroll
    for (int k = 0; k < 4; k++) {
        h[k] = __float2bfloat16(f[k]);
        l[k] = __float2bfloat16(f[k] - __bfloat162float(h[k]));
    }
    __nv_bfloat162* hp = reinterpret_cast<__nv_bfloat162*>(hi) + i * 2;
    __nv_bfloat162* lp = reinterpret_cast<__nv_bfloat162*>(lo) + i * 2;
    hp[0] = __nv_bfloat162(h[0], h[1]);
    hp[1] = __nv_bfloat162(h[2], h[3]);
    lp[0] = __nv_bfloat162(l[0], l[1]);
    lp[1] = __nv_bfloat162(l[2], l[3]);
}

// ---------------------------------------------------------------------------
// Transpose + split: W [K,N] fp32 row-major -> Wt [N,K] bf16 hi/lo
// ---------------------------------------------------------------------------
__global__ __launch_bounds__(256)
void transpose_split_kernel(const float* __restrict__ W,
                            __nv_bfloat16* __restrict__ Th,
                            __nv_bfloat16* __restrict__ Tl)
{
    __shared__ float t[32][33];
    int bx = blockIdx.x * 32;   // N
    int by = blockIdx.y * 32;   // K
    int x = threadIdx.x, y = threadIdx.y;
    #pragma unroll
    for (int j = 0; j < 32; j += 8)
        t[y + j][x] = W[(size_t)(by + y + j) * DOUT + bx + x];
    __syncthreads();
    #pragma unroll
    for (int j = 0; j < 32; j += 8) {
        float v = t[x][y + j];
        __nv_bfloat16 h = __float2bfloat16(v);
        __nv_bfloat16 l = __float2bfloat16(v - __bfloat162float(h));
        size_t o = (size_t)(bx + y + j) * DIN + by + x;
        Th[o] = h;
        Tl[o] = l;
    }
}

// ---------------------------------------------------------------------------
// cp.async-pipelined HMMA GEMM, split-bf16 3-term accumulation.
// CTA tile 128x128, K-tile 32, 2-stage smem pipeline, 2 CTAs/SM.
// QKV=true : fused N=3072 (Wq|Wk|Wv rows contiguous); epilogue emits fp16
//            hi/lo splits directly (Q scaled by 0.125).
// QKV=false: fp32 + bias epilogue (output projection).
// ---------------------------------------------------------------------------
#define CTM 128
#define CTN 128
#define CTK 32
#define KPAD 40                      // halves per smem row (80 B)
#define GKIT (DIN / CTK)             // 32
#define TO_AH 0
#define TO_AL 10240                  // 128*80
#define TO_BH 20480
#define TO_BL 30720
#define STAGE_B 40960
#define GEMM_SMEM (2 * STAGE_B)      // 81920

template<bool QKV>
__global__ __launch_bounds__(256, 2)
void gemm_pipe(const __nv_bfloat16* __restrict__ Ah, const __nv_bfloat16* __restrict__ Al,
               const __nv_bfloat16* __restrict__ Bh, const __nv_bfloat16* __restrict__ Bl,
               const float* __restrict__ bias, float* __restrict__ C,
               __half* __restrict__ O0h, __half* __restrict__ O0l,
               __half* __restrict__ O1h, __half* __restrict__ O1l,
               __half* __restrict__ O2h, __half* __restrict__ O2l)
{
    extern __shared__ __align__(16) char sm_raw[];
    const uint32_t su = smem_u32(sm_raw);

    const int tid  = threadIdx.x;
    const int w    = tid >> 5;
    const int lane = tid & 31;
    const int wm   = w >> 2;            // 0..1
    const int wn   = w & 3;             // 0..3
    const int bm   = blockIdx.y * CTM;
    const int bn   = blockIdx.x * CTN;

    const int arow = wm * 64 + (lane & 15);
    const int brow = wn * 32 + (lane & 15);
    const int khalf = (lane >> 4) * 8;

    float acc[4][4][4];
    #pragma unroll
    for (int mt = 0; mt < 4; mt++)
        #pragma unroll
        for (int nt = 0; nt < 4; nt++)
            #pragma unroll
            for (int e = 0; e < 4; e++) acc[mt][nt][e] = 0.f;

    #define ISSUE(it_, buf_) do {                                              \
        const int k0_ = (it_) * CTK;                                           \
        const uint32_t sb_ = su + (buf_) * STAGE_B;                            \
        _Pragma("unroll")                                                      \
        for (int t = 0; t < 2; t++) {                                          \
            int u = tid + t * 256;                                             \
            int row = u >> 2, cs = u & 3;                                      \
            size_t ga = (size_t)(bm + row) * 1024 + k0_ + cs * 8;              \
            size_t gb = (size_t)(bn + row) * 1024 + k0_ + cs * 8;              \
            uint32_t off = row * 80 + cs * 16;                                 \
            cp16(sb_ + TO_AH + off, Ah + ga);                                  \
            cp16(sb_ + TO_AL + off, Al + ga);                                  \
            cp16(sb_ + TO_BH + off, Bh + gb);                                  \
            cp16(sb_ + TO_BL + off, Bl + gb);                                  \
        }                                                                      \
    } while (0)

    ISSUE(0, 0);
    CP_COMMIT();

    for (int it = 0; it < GKIT; it++) {
        if (it + 1 < GKIT) {
            ISSUE(it + 1, (it + 1) & 1);
            CP_COMMIT();
            CP_WAIT1();
        } else {
            CP_WAIT0();
        }
        __syncthreads();

        const uint32_t sb = su + (it & 1) * STAGE_B;
        const uint32_t uAh = sb + TO_AH, uAl = sb + TO_AL;
        const uint32_t uBh = sb + TO_BH, uBl = sb + TO_BL;

        #pragma unroll
        for (int ks = 0; ks < 2; ks++) {
            const int kb = ks * 16 + khalf;
            uint32_t bh[8], bl[8];
            ldsm4(bh + 0, uBh + (brow +  0) * 80 + kb * 2);
            ldsm4(bh + 4, uBh + (brow + 16) * 80 + kb * 2);
            ldsm4(bl + 0, uBl + (brow +  0) * 80 + kb * 2);
            ldsm4(bl + 4, uBl + (brow + 16) * 80 + kb * 2);

            #pragma unroll
            for (int mt = 0; mt < 4; mt++) {
                uint32_t ah[4], al[4];
                ldsm4(ah, uAh + (arow + mt * 16) * 80 + kb * 2);
                ldsm4(al, uAl + (arow + mt * 16) * 80 + kb * 2);
                #pragma unroll
                for (int nt = 0; nt < 4; nt++) {
                    const int i0 = 4 * (nt >> 1) + (nt & 1);
                    mma_bf16(acc[mt][nt], ah, bh[i0], bh[i0 + 2]);
                    mma_bf16(acc[mt][nt], al, bh[i0], bh[i0 + 2]);
                    mma_bf16(acc[mt][nt], ah, bl[i0], bl[i0 + 2]);
                }
            }
        }
        __syncthreads();
    }
    #undef ISSUE

    const int erow = bm + wm * 64 + (lane >> 2);

    if (QKV) {
        // route to Q/K/V fp16 split outputs
        const int tsel = bn >> 10;
        const int cloc = (bn & 1023) + wn * 32;
        __half* Oh = (tsel == 0) ? O0h : (tsel == 1) ? O1h : O2h;
        __half* Ol = (tsel == 0) ? O0l : (tsel == 1) ? O1l : O2l;
        const float scl = (tsel == 0) ? 0.125f : 1.0f;
        #pragma unroll
        for (int nt = 0; nt < 4; nt++) {
            const int col = cloc + nt * 8 + (lane & 3) * 2;
            #pragma unroll
            for (int mt = 0; mt < 4; mt++) {
                #pragma unroll
                for (int rh = 0; rh < 2; rh++) {
                    const size_t row = (size_t)(erow + mt * 16 + rh * 8);
                    const float v0 = acc[mt][nt][2 * rh]     * scl;
                    const float v1 = acc[mt][nt][2 * rh + 1] * scl;
                    const __half h0 = __float2half_rn(v0);
                    const __half h1 = __float2half_rn(v1);
                    const __half l0 = __float2half_rn(v0 - __half2float(h0));
                    const __half l1 = __float2half_rn(v1 - __half2float(h1));
                    *reinterpret_cast<uint32_t*>(Oh + row * 1024 + col) = pack_h2(h0, h1);
                    *reinterpret_cast<uint32_t*>(Ol + row * 1024 + col) = pack_h2(l0, l1);
                }
            }
        }
    } else {
        #pragma unroll
        for (int nt = 0; nt < 4; nt++) {
            const int col = bn + wn * 32 + nt * 8 + (lane & 3) * 2;
            const float bx = bias ? bias[col] : 0.f;
            const float by = bias ? bias[col + 1] : 0.f;
            #pragma unroll
            for (int mt = 0; mt < 4; mt++) {
                const int r0 = erow + mt * 16;
                float2 v0 = make_float2(acc[mt][nt][0] + bx, acc[mt][nt][1] + by);
                float2 v1 = make_float2(acc[mt][nt][2] + bx, acc[mt][nt][3] + by);
                *reinterpret_cast<float2*>(C + (size_t)r0 * DOUT + col) = v0;
                *reinterpret_cast<float2*>(C + (size_t)(r0 + 8) * DOUT + col) = v1;
            }
        }
    }
}

// ---------------------------------------------------------------------------
// HMMA flash attention (split fp16, 3-MMA). CTA = 128 q-rows x one (b,h).
// Epilogue emits bf16 hi/lo ctx splits directly for the output projection.
// ---------------------------------------------------------------------------
#define ABQ 128
#define AKV 64
#define AST 72
#define KVT_H (AKV * AST)
#define STAGE_H (4 * KVT_H)
#define ASMEM_B (2 * STAGE_H * 2)       // 73728 bytes

__global__ __launch_bounds__(256, 1)
void attn_mma(const __half* __restrict__ Qh, const __half* __restrict__ Ql,
              const __half* __restrict__ Kh, const __half* __restrict__ Kl,
              const __half* __restrict__ Vh, const __half* __restrict__ Vl,
              __nv_bfloat16* __restrict__ Ch, __nv_bfloat16* __restrict__ Cl)
{
    extern __shared__ __align__(16) __half s[];
    const uint32_t sbase = smem_u32(s);

    const int tid  = threadIdx.x;
    const int w    = tid >> 5;
    const int lane = tid & 31;

    const int qt = (int)gridDim.x - 1 - (int)blockIdx.x;   // heavy first
    const int bh = blockIdx.y;
    const int b  = bh >> 4;
    const int h  = bh & 15;

    const size_t rowbase = (size_t)b * SEQ;
    const int    colbase = h * HDIM;
    const int    qbase   = qt * ABQ;
    const int    wq      = qbase + w * 16;

    // ---- stage Q hi/lo, load A fragments ----
    {
        #pragma unroll
        for (int t = 0; t < 4; t++) {
            int u = tid + t * 256;
            int row = u >> 3, seg = u & 7;
            uint4 vh4 = *reinterpret_cast<const uint4*>(
                Qh + (rowbase + qbase + row) * 1024 + colbase + seg * 8);
            uint4 vl4 = *reinterpret_cast<const uint4*>(
                Ql + (rowbase + qbase + row) * 1024 + colbase + seg * 8);
            *reinterpret_cast<uint4*>(s + row * AST + seg * 8) = vh4;
            *reinterpret_cast<uint4*>(s + ABQ * AST + row * AST + seg * 8) = vl4;
        }
    }
    __syncthreads();

    uint32_t qfh[4][4], qfl[4][4];
    {
        const int arow = w * 16 + (lane & 15);
        const int k8   = (lane >> 4) * 8;
        #pragma unroll
        for (int ks = 0; ks < 4; ks++) {
            ldsm4(qfh[ks], sbase + (arow * AST + ks * 16 + k8) * 2);
            ldsm4(qfl[ks], sbase + ((ABQ * AST) + arow * AST + ks * 16 + k8) * 2);
        }
    }
    __syncthreads();

    float ctx[8][4];
    #pragma unroll
    for (int nt = 0; nt < 8; nt++)
        #pragma unroll
        for (int e = 0; e < 4; e++) ctx[nt][e] = 0.f;
    float mrow[2] = {-1e30f, -1e30f};
    float lrow[2] = {0.f, 0.f};

    const int nkt = 2 * qt + 2;

    uint4 rg[8];
    #define AGLD(kt_) do {                                                     \
        const __half* gt0[4] = {Kh, Kl, Vh, Vl};                               \
        _Pragma("unroll")                                                      \
        for (int tn = 0; tn < 4; tn++)                                         \
            _Pragma("unroll")                                                  \
            for (int t = 0; t < 2; t++) {                                      \
                int u = tid + t * 256;                                         \
                int row = u >> 3, seg = u & 7;                                 \
                rg[tn * 2 + t] = *reinterpret_cast<const uint4*>(              \
                    gt0[tn] + (rowbase + (kt_) * AKV + row) * 1024             \
                            + colbase + seg * 8);                              \
            }                                                                  \
    } while (0)
    #define ASTS(buf_) do {                                                    \
        __half* sb = s + (buf_) * STAGE_H;                                     \
        _Pragma("unroll")                                                      \
        for (int tn = 0; tn < 4; tn++)                                         \
            _Pragma("unroll")                                                  \
            for (int t = 0; t < 2; t++) {                                      \
                int u = tid + t * 256;                                         \
                int row = u >> 3, seg = u & 7;                                 \
                *reinterpret_cast<uint4*>(sb + tn * KVT_H + row * AST          \
                                          + seg * 8) = rg[tn * 2 + t];         \
            }                                                                  \
    } while (0)

    AGLD(0);
    ASTS(0);
    __syncthreads();

    for (int kt = 0; kt < nkt; kt++) {
        const int buf = kt & 1;
        if (kt + 1 < nkt) AGLD(kt + 1);

        const bool skip = (kt * AKV) > (wq + 15);
        if (!skip) {
            const uint32_t kh_b = sbase + (buf * STAGE_H + 0 * KVT_H) * 2;
            const uint32_t kl_b = sbase + (buf * STAGE_H + 1 * KVT_H) * 2;
            const uint32_t vh_b = sbase + (buf * STAGE_H + 2 * KVT_H) * 2;
            const uint32_t vl_b = sbase + (buf * STAGE_H + 3 * KVT_H) * 2;

            // ---- S = Q K^T ----
            float sv[8][4];
            #pragma unroll
            for (int nt = 0; nt < 8; nt++)
                #pragma unroll
                for (int e = 0; e < 4; e++) sv[nt][e] = 0.f;

            const int brow = lane & 15;
            const int k8   = (lane >> 4) * 8;
            #pragma unroll
            for (int ks = 0; ks < 4; ks++) {
                #pragma unroll
                for (int np = 0; np < 4; np++) {
                    uint32_t kh4[4], kl4[4];
                    const uint32_t off = ((np * 16 + brow) * AST + ks * 16 + k8) * 2;
                    ldsm4(kh4, kh_b + off);
                    ldsm4(kl4, kl_b + off);
                    mma_f16(sv[2 * np],     qfh[ks], kh4[0], kh4[2]);
                    mma_f16(sv[2 * np],     qfl[ks], kh4[0], kh4[2]);
                    mma_f16(sv[2 * np],     qfh[ks], kl4[0], kl4[2]);
                    mma_f16(sv[2 * np + 1], qfh[ks], kh4[1], kh4[3]);
                    mma_f16(sv[2 * np + 1], qfl[ks], kh4[1], kh4[3]);
                    mma_f16(sv[2 * np + 1], qfh[ks], kl4[1], kl4[3]);
                }
            }

            // ---- causal mask ----
            if (kt * AKV + AKV - 1 > wq) {
                const int qr = wq + (lane >> 2);
                #pragma unroll
                for (int nt = 0; nt < 8; nt++) {
                    const int kg0 = kt * AKV + nt * 8 + (lane & 3) * 2;
                    #pragma unroll
                    for (int e = 0; e < 4; e++) {
                        const int qg = qr + ((e >> 1) << 3);
                        const int kg = kg0 + (e & 1);
                        if (kg > qg) sv[nt][e] = -1e30f;
                    }
                }
            }

            // ---- online softmax ----
            float alpha[2];
            #pragma unroll
            for (int rr = 0; rr < 2; rr++) {
                float rmax = -1e30f;
                #pragma unroll
                for (int nt = 0; nt < 8; nt++)
                    rmax = fmaxf(rmax, fmaxf(sv[nt][2 * rr], sv[nt][2 * rr + 1]));
                rmax = fmaxf(rmax, __shfl_xor_sync(0xffffffffu, rmax, 1));
                rmax = fmaxf(rmax, __shfl_xor_sync(0xffffffffu, rmax, 2));
                const float mnew = fmaxf(mrow[rr], rmax);
                alpha[rr] = __expf(mrow[rr] - mnew);
                float rsum = 0.f;
                #pragma unroll
                for (int nt = 0; nt < 8; nt++) {
                    float p0 = __expf(sv[nt][2 * rr]     - mnew);
                    float p1 = __expf(sv[nt][2 * rr + 1] - mnew);
                    sv[nt][2 * rr] = p0; sv[nt][2 * rr + 1] = p1;
                    rsum += p0 + p1;
                }
                rsum += __shfl_xor_sync(0xffffffffu, rsum, 1);
                rsum += __shfl_xor_sync(0xffffffffu, rsum, 2);
                lrow[rr] = lrow[rr] * alpha[rr] + rsum;
                mrow[rr] = mnew;
            }
            #pragma unroll
            for (int nt = 0; nt < 8; nt++) {
                ctx[nt][0] *= alpha[0]; ctx[nt][1] *= alpha[0];
                ctx[nt][2] *= alpha[1]; ctx[nt][3] *= alpha[1];
            }

            // ---- pack P fragments (fp16 hi/lo) ----
            uint32_t pah[4][4], pal[4][4];
            #pragma unroll
            for (int t = 0; t < 4; t++) {
                #pragma unroll
                for (int h2 = 0; h2 < 4; h2++) {
                    const int nt = 2 * t + (h2 >> 1);
                    const int e0 = (h2 & 1) * 2;
                    const float a0 = sv[nt][e0], a1 = sv[nt][e0 + 1];
                    const __half h0 = __float2half_rn(a0);
                    const __half h1 = __float2half_rn(a1);
                    pah[t][h2] = pack_h2(h0, h1);
                    pal[t][h2] = pack_h2(
                        __float2half_rn(a0 - __half2float(h0)),
                        __float2half_rn(a1 - __half2float(h1)));
                }
            }

            // ---- ctx += P V ----
            #pragma unroll
            for (int t = 0; t < 4; t++) {
                #pragma unroll
                for (int dp = 0; dp < 4; dp++) {
                    uint32_t vh4[4], vl4[4];
                    const uint32_t off =
                        ((t * 16 + (lane & 15)) * AST + dp * 16 + k8) * 2;
                    ldsm4t(vh4, vh_b + off);
                    ldsm4t(vl4, vl_b + off);
                    mma_f16(ctx[2 * dp],     pah[t], vh4[0], vh4[1]);
                    mma_f16(ctx[2 * dp],     pal[t], vh4[0], vh4[1]);
                    mma_f16(ctx[2 * dp],     pah[t], vl4[0], vl4[1]);
                    mma_f16(ctx[2 * dp + 1], pah[t], vh4[2], vh4[3]);
                    mma_f16(ctx[2 * dp + 1], pal[t], vh4[2], vh4[3]);
                    mma_f16(ctx[2 * dp + 1], pah[t], vl4[2], vl4[3]);
                }
            }
        }

        if (kt + 1 < nkt) ASTS(buf ^ 1);
        __syncthreads();
    }

    // ---- epilogue: ctx /= l, write bf16 hi/lo splits ----
    #pragma unroll
    for (int rr = 0; rr < 2; rr++) {
        const float inv = 1.f / lrow[rr];
        const size_t row = rowbase + qbase + w * 16 + (lane >> 2) + rr * 8;
        #pragma unroll
        for (int nt = 0; nt < 8; nt++) {
            const int col = colbase + nt * 8 + (lane & 3) * 2;
            const float v0 = ctx[nt][2 * rr] * inv;
            const float v1 = ctx[nt][2 * rr + 1] * inv;
            const __nv_bfloat16 h0 = __float2bfloat16(v0);
            const __nv_bfloat16 h1 = __float2bfloat16(v1);
            const __nv_bfloat16 l0 = __float2bfloat16(v0 - __bfloat162float(h0));
            const __nv_bfloat16 l1 = __float2bfloat16(v1 - __bfloat162float(h1));
            *reinterpret_cast<__nv_bfloat162*>(Ch + row * 1024 + col) =
                __nv_bfloat162(h0, h1);
            *reinterpret_cast<__nv_bfloat162*>(Cl + row * 1024 + col) =
                __nv_bfloat162(l0, l1);
        }
    }
    #undef AGLD
    #undef ASTS
}

// ---------------------------------------------------------------------------
// Launcher
// ---------------------------------------------------------------------------
extern "C" void kernel_launch(void* const* d_in, const int* in_sizes, int n_in,
                              void* d_out, int out_size)
{
    const float* x  = (const float*)d_in[0];
    const float* Wq = (const float*)d_in[1];
    const float* Wk = (const float*)d_in[2];
    const float* Wv = (const float*)d_in[3];
    const float* Wo = (const float*)d_in[4];
    const float* bo = (const float*)d_in[5];
    float* out = (float*)d_out;

    __nv_bfloat16 *xh, *xl, *ch, *cl, *Wth, *Wtl;
    cudaGetSymbolAddress((void**)&xh,  g_xh);
    cudaGetSymbolAddress((void**)&xl,  g_xl);
    cudaGetSymbolAddress((void**)&ch,  g_ctxh);
    cudaGetSymbolAddress((void**)&cl,  g_ctxl);
    cudaGetSymbolAddress((void**)&Wth, g_Wth);
    cudaGetSymbolAddress((void**)&Wtl, g_Wtl);
    __half *qhh, *qhl, *khh, *khl, *vhh, *vhl;
    cudaGetSymbolAddress((void**)&qhh, g_Qh);
    cudaGetSymbolAddress((void**)&qhl, g_Ql);
    cudaGetSymbolAddress((void**)&khh, g_Kh);
    cudaGetSymbolAddress((void**)&khl, g_Kl);
    cudaGetSymbolAddress((void**)&vhh, g_Vh);
    cudaGetSymbolAddress((void**)&vhl, g_Vl);

    const int n4 = MROWS * DIN / 4;

    // split x -> bf16 hi/lo
    split_kernel<<<(n4 + 255) / 256, 256>>>(x, xh, xl, n4);

    // transpose + split the four weight matrices
    dim3 tb(32, 8), tg(32, 32);
    transpose_split_kernel<<<tg, tb>>>(Wq, Wth + 0 * WELEM, Wtl + 0 * WELEM);
    transpose_split_kernel<<<tg, tb>>>(Wk, Wth + 1 * WELEM, Wtl + 1 * WELEM);
    transpose_split_kernel<<<tg, tb>>>(Wv, Wth + 2 * WELEM, Wtl + 2 * WELEM);
    transpose_split_kernel<<<tg, tb>>>(Wo, Wth + 3 * WELEM, Wtl + 3 * WELEM);

    // fused QKV GEMM (N = 3072), epilogue writes fp16 hi/lo splits
    cudaFuncSetAttribute(gemm_pipe<true>,
                         cudaFuncAttributeMaxDynamicSharedMemorySize, GEMM_SMEM);
    cudaFuncSetAttribute(gemm_pipe<false>,
                         cudaFuncAttributeMaxDynamicSharedMemorySize, GEMM_SMEM);
    dim3 gq(3 * DOUT / CTN, MROWS / CTM);   // (24, 32)
    gemm_pipe<true><<<gq, 256, GEMM_SMEM>>>(xh, xl, Wth, Wtl, nullptr, nullptr,
                                            qhh, qhl, khh, khl, vhh, vhl);

    // HMMA flash attention -> bf16 hi/lo ctx
    cudaFuncSetAttribute(attn_mma, cudaFuncAttributeMaxDynamicSharedMemorySize,
                         ASMEM_B);
    dim3 attn_grid(SEQ / ABQ, BATCH * NHEADS);   // (16, 32)
    attn_mma<<<attn_grid, 256, ASMEM_B>>>(qhh, qhl, khh, khl, vhh, vhl, ch, cl);

    // output projection (with bias)
    dim3 go(DOUT / CTN, MROWS / CTM);       // (8, 32)
    gemm_pipe<false><<<go, 256, GEMM_SMEM>>>(ch, cl, Wth + 3 * WELEM, Wtl + 3 * WELEM,
                                             bo, out,
                                             nullptr, nullptr, nullptr, nullptr,
                                             nullptr, nullptr);
}

// round 12
// speedup vs baseline: 3.5174x; 1.3369x over previous
#include <cuda_runtime.h>
#include <cuda_bf16.h>
#include <cuda_fp16.h>
#include <cstdint>

// Problem constants
#define BATCH   2
#define SEQ     2048
#define DIN     1024
#define DOUT    1024
#define NHEADS  16
#define HDIM    64
#define MROWS   (BATCH * SEQ)        // 4096
#define WELEM   (DIN * DOUT)         // 1M

// ---------------------------------------------------------------------------
// Scratch (device globals — no runtime allocation allowed)
// ---------------------------------------------------------------------------
__device__ __half g_xh[MROWS * DIN];         // x split hi
__device__ __half g_xl[MROWS * DIN];         // x split lo
__device__ __half g_Wt[4 * WELEM];           // transposed weights [N,K], fp16 hi only
__device__ __half g_Qh[MROWS * DOUT];
__device__ __half g_Ql[MROWS * DOUT];
__device__ __half g_Kh[MROWS * DOUT];        // K: hi only (S is Q-corrected)
__device__ __half g_Vh[MROWS * DOUT];
__device__ __half g_Vl[MROWS * DOUT];
__device__ __half g_Ch[MROWS * DOUT];        // ctx split hi
__device__ __half g_Cl[MROWS * DOUT];        // ctx split lo

// ---------------------------------------------------------------------------
// Warp-MMA / async-copy helpers (baseline PTX ISA, no arch-"a" features)
// ---------------------------------------------------------------------------
__device__ __forceinline__ uint32_t smem_u32(const void* p) {
    uint32_t a;
    asm("{ .reg .u64 t; cvta.to.shared.u64 t, %1; cvt.u32.u64 %0, t; }"
        : "=r"(a) : "l"(p));
    return a;
}
__device__ __forceinline__ void ldsm4(uint32_t* r, uint32_t addr) {
    asm volatile("ldmatrix.sync.aligned.m8n8.x4.shared.b16 {%0,%1,%2,%3}, [%4];"
                 : "=r"(r[0]), "=r"(r[1]), "=r"(r[2]), "=r"(r[3]) : "r"(addr));
}
__device__ __forceinline__ void ldsm4t(uint32_t* r, uint32_t addr) {
    asm volatile("ldmatrix.sync.aligned.m8n8.x4.trans.shared.b16 {%0,%1,%2,%3}, [%4];"
                 : "=r"(r[0]), "=r"(r[1]), "=r"(r[2]), "=r"(r[3]) : "r"(addr));
}
__device__ __forceinline__ void mma_f16(float* c, const uint32_t* a,
                                        uint32_t b0, uint32_t b1) {
    asm volatile(
        "mma.sync.aligned.m16n8k16.row.col.f32.f16.f16.f32 "
        "{%0,%1,%2,%3}, {%4,%5,%6,%7}, {%8,%9}, {%0,%1,%2,%3};"
        : "+f"(c[0]), "+f"(c[1]), "+f"(c[2]), "+f"(c[3])
        : "r"(a[0]), "r"(a[1]), "r"(a[2]), "r"(a[3]), "r"(b0), "r"(b1));
}
__device__ __forceinline__ void cp16(uint32_t dst, const void* src) {
    asm volatile("cp.async.cg.shared.global [%0], [%1], 16;"
                 :: "r"(dst), "l"(src));
}
#define CP_COMMIT() asm volatile("cp.async.commit_group;" ::: "memory")
#define CP_WAIT1()  asm volatile("cp.async.wait_group 1;" ::: "memory")
#define CP_WAIT0()  asm volatile("cp.async.wait_group 0;" ::: "memory")

__device__ __forceinline__ uint32_t pack_h2(__half a, __half b) {
    __half2 h = __halves2half2(a, b);
    return *reinterpret_cast<uint32_t*>(&h);
}

// ---------------------------------------------------------------------------
// Split fp32 -> (hi, lo) fp16, with scale folded in
// ---------------------------------------------------------------------------
__global__ __launch_bounds__(256)
void split_half_kernel(const float* __restrict__ in, __half* __restrict__ hi,
                       __half* __restrict__ lo, float scale, int n4)
{
    int i = blockIdx.x * blockDim.x + threadIdx.x;
    if (i >= n4) return;
    float4 v = reinterpret_cast<const float4*>(in)[i];
    float f[4] = {v.x * scale, v.y * scale, v.z * scale, v.w * scale};
    __half h[4], l[4];
    #pragma unroll
    for (int k = 0; k < 4; k++) {
        h[k] = __float2half_rn(f[k]);
        l[k] = __float2half_rn(f[k] - __half2float(h[k]));
    }
    uint2 hp = make_uint2(pack_h2(h[0], h[1]), pack_h2(h[2], h[3]));
    uint2 lp = make_uint2(pack_h2(l[0], l[1]), pack_h2(l[2], l[3]));
    reinterpret_cast<uint2*>(hi)[i] = hp;
    reinterpret_cast<uint2*>(lo)[i] = lp;
}

// ---------------------------------------------------------------------------
// Transpose: W [K,N] fp32 row-major -> Wt [N,K] fp16 (hi only)
// ---------------------------------------------------------------------------
__global__ __launch_bounds__(256)
void transpose_half_kernel(const float* __restrict__ W, __half* __restrict__ T)
{
    __shared__ float t[32][33];
    int bx = blockIdx.x * 32;   // N
    int by = blockIdx.y * 32;   // K
    int x = threadIdx.x, y = threadIdx.y;
    #pragma unroll
    for (int j = 0; j < 32; j += 8)
        t[y + j][x] = W[(size_t)(by + y + j) * DOUT + bx + x];
    __syncthreads();
    #pragma unroll
    for (int j = 0; j < 32; j += 8)
        T[(size_t)(bx + y + j) * DIN + by + x] = __float2half_rn(t[x][y + j]);
}

// ---------------------------------------------------------------------------
// cp.async-pipelined HMMA GEMM, 2-term fp16:  C = (Ah + Al) @ Bh^T (+bias)
// CTA tile 128x128, K-tile 32, 2-stage pipeline, 2 CTAs/SM.
// QKV=true : fused N=3072; epilogue emits Q hi/lo (x0.125), K hi, V hi/lo.
// QKV=false: fp32 + bias epilogue (output projection).
// ---------------------------------------------------------------------------
#define CTM 128
#define CTN 128
#define CTK 32
#define GKIT (DIN / CTK)             // 32
#define TO_AH 0
#define TO_AL 10240                  // 128*80
#define TO_BH 20480
#define STAGE_B 30720
#define GEMM_SMEM (2 * STAGE_B)      // 61440

template<bool QKV>
__global__ __launch_bounds__(256, 2)
void gemm_pipe(const __half* __restrict__ Ah, const __half* __restrict__ Al,
               const __half* __restrict__ Bh,
               const float* __restrict__ bias, float* __restrict__ C,
               __half* __restrict__ O0h, __half* __restrict__ O0l,
               __half* __restrict__ O1h,
               __half* __restrict__ O2h, __half* __restrict__ O2l)
{
    extern __shared__ __align__(16) char sm_raw[];
    const uint32_t su = smem_u32(sm_raw);

    const int tid  = threadIdx.x;
    const int w    = tid >> 5;
    const int lane = tid & 31;
    const int wm   = w >> 2;            // 0..1
    const int wn   = w & 3;             // 0..3
    const int bm   = blockIdx.y * CTM;
    const int bn   = blockIdx.x * CTN;

    const int arow = wm * 64 + (lane & 15);
    const int brow = wn * 32 + (lane & 15);
    const int khalf = (lane >> 4) * 8;

    float acc[4][4][4];
    #pragma unroll
    for (int mt = 0; mt < 4; mt++)
        #pragma unroll
        for (int nt = 0; nt < 4; nt++)
            #pragma unroll
            for (int e = 0; e < 4; e++) acc[mt][nt][e] = 0.f;

    #define ISSUE(it_, buf_) do {                                              \
        const int k0_ = (it_) * CTK;                                           \
        const uint32_t sb_ = su + (buf_) * STAGE_B;                            \
        _Pragma("unroll")                                                      \
        for (int t = 0; t < 2; t++) {                                          \
            int u = tid + t * 256;                                             \
            int row = u >> 2, cs = u & 3;                                      \
            size_t ga = (size_t)(bm + row) * 1024 + k0_ + cs * 8;              \
            size_t gb = (size_t)(bn + row) * 1024 + k0_ + cs * 8;              \
            uint32_t off = row * 80 + cs * 16;                                 \
            cp16(sb_ + TO_AH + off, Ah + ga);                                  \
            cp16(sb_ + TO_AL + off, Al + ga);                                  \
            cp16(sb_ + TO_BH + off, Bh + gb);                                  \
        }                                                                      \
    } while (0)

    ISSUE(0, 0);
    CP_COMMIT();

    for (int it = 0; it < GKIT; it++) {
        if (it + 1 < GKIT) {
            ISSUE(it + 1, (it + 1) & 1);
            CP_COMMIT();
            CP_WAIT1();
        } else {
            CP_WAIT0();
        }
        __syncthreads();

        const uint32_t sb = su + (it & 1) * STAGE_B;
        const uint32_t uAh = sb + TO_AH, uAl = sb + TO_AL, uBh = sb + TO_BH;

        #pragma unroll
        for (int ks = 0; ks < 2; ks++) {
            const int kb = ks * 16 + khalf;
            uint32_t bh[8];
            ldsm4(bh + 0, uBh + (brow +  0) * 80 + kb * 2);
            ldsm4(bh + 4, uBh + (brow + 16) * 80 + kb * 2);

            #pragma unroll
            for (int mt = 0; mt < 4; mt++) {
                uint32_t ah[4], al[4];
                ldsm4(ah, uAh + (arow + mt * 16) * 80 + kb * 2);
                ldsm4(al, uAl + (arow + mt * 16) * 80 + kb * 2);
                #pragma unroll
                for (int nt = 0; nt < 4; nt++) {
                    const int i0 = 4 * (nt >> 1) + (nt & 1);
                    mma_f16(acc[mt][nt], ah, bh[i0], bh[i0 + 2]);
                    mma_f16(acc[mt][nt], al, bh[i0], bh[i0 + 2]);
                }
            }
        }
        __syncthreads();
    }
    #undef ISSUE

    const int erow = bm + wm * 64 + (lane >> 2);

    if (QKV) {
        const int tsel = bn >> 10;              // 0=Q, 1=K, 2=V
        const int cloc = (bn & 1023) + wn * 32;
        __half* Oh = (tsel == 0) ? O0h : (tsel == 1) ? O1h : O2h;
        __half* Ol = (tsel == 0) ? O0l : O2l;   // unused for K
        const bool wlo = (tsel != 1);
        const float scl = (tsel == 0) ? 0.125f : 1.0f;
        #pragma unroll
        for (int nt = 0; nt < 4; nt++) {
            const int col = cloc + nt * 8 + (lane & 3) * 2;
            #pragma unroll
            for (int mt = 0; mt < 4; mt++) {
                #pragma unroll
                for (int rh = 0; rh < 2; rh++) {
                    const size_t row = (size_t)(erow + mt * 16 + rh * 8);
                    const float v0 = acc[mt][nt][2 * rh]     * scl;
                    const float v1 = acc[mt][nt][2 * rh + 1] * scl;
                    const __half h0 = __float2half_rn(v0);
                    const __half h1 = __float2half_rn(v1);
                    *reinterpret_cast<uint32_t*>(Oh + row * 1024 + col) = pack_h2(h0, h1);
                    if (wlo) {
                        const __half l0 = __float2half_rn(v0 - __half2float(h0));
                        const __half l1 = __float2half_rn(v1 - __half2float(h1));
                        *reinterpret_cast<uint32_t*>(Ol + row * 1024 + col) = pack_h2(l0, l1);
                    }
                }
            }
        }
    } else {
        #pragma unroll
        for (int nt = 0; nt < 4; nt++) {
            const int col = bn + wn * 32 + nt * 8 + (lane & 3) * 2;
            const float bx = bias ? bias[col] : 0.f;
            const float by = bias ? bias[col + 1] : 0.f;
            #pragma unroll
            for (int mt = 0; mt < 4; mt++) {
                const int r0 = erow + mt * 16;
                float2 v0 = make_float2(acc[mt][nt][0] + bx, acc[mt][nt][1] + by);
                float2 v1 = make_float2(acc[mt][nt][2] + bx, acc[mt][nt][3] + by);
                *reinterpret_cast<float2*>(C + (size_t)r0 * DOUT + col) = v0;
                *reinterpret_cast<float2*>(C + (size_t)(r0 + 8) * DOUT + col) = v1;
            }
        }
    }
}

// ---------------------------------------------------------------------------
// HMMA flash attention.  S: 2-term (Q corrected, K hi-only).
// PV: 3-term (P and V corrected).  Epilogue: fp16 hi/lo ctx splits.
// ---------------------------------------------------------------------------
#define ABQ 128
#define AKV 64
#define AST 72
#define KVT_H (AKV * AST)               // 4608 halves
#define STAGE_H (3 * KVT_H)             // Kh | Vh | Vl
#define ASMEM_B (2 * STAGE_H * 2)       // 55296 bytes

__global__ __launch_bounds__(256, 1)
void attn_mma(const __half* __restrict__ Qh, const __half* __restrict__ Ql,
              const __half* __restrict__ Kh,
              const __half* __restrict__ Vh, const __half* __restrict__ Vl,
              __half* __restrict__ Ch, __half* __restrict__ Cl)
{
    extern __shared__ __align__(16) __half s[];
    const uint32_t sbase = smem_u32(s);

    const int tid  = threadIdx.x;
    const int w    = tid >> 5;
    const int lane = tid & 31;

    const int qt = (int)gridDim.x - 1 - (int)blockIdx.x;   // heavy first
    const int bh = blockIdx.y;
    const int b  = bh >> 4;
    const int h  = bh & 15;

    const size_t rowbase = (size_t)b * SEQ;
    const int    colbase = h * HDIM;
    const int    qbase   = qt * ABQ;
    const int    wq      = qbase + w * 16;

    // ---- stage Q hi/lo, load A fragments ----
    {
        #pragma unroll
        for (int t = 0; t < 4; t++) {
            int u = tid + t * 256;
            int row = u >> 3, seg = u & 7;
            uint4 vh4 = *reinterpret_cast<const uint4*>(
                Qh + (rowbase + qbase + row) * 1024 + colbase + seg * 8);
            uint4 vl4 = *reinterpret_cast<const uint4*>(
                Ql + (rowbase + qbase + row) * 1024 + colbase + seg * 8);
            *reinterpret_cast<uint4*>(s + row * AST + seg * 8) = vh4;
            *reinterpret_cast<uint4*>(s + ABQ * AST + row * AST + seg * 8) = vl4;
        }
    }
    __syncthreads();

    uint32_t qfh[4][4], qfl[4][4];
    {
        const int arow = w * 16 + (lane & 15);
        const int k8   = (lane >> 4) * 8;
        #pragma unroll
        for (int ks = 0; ks < 4; ks++) {
            ldsm4(qfh[ks], sbase + (arow * AST + ks * 16 + k8) * 2);
            ldsm4(qfl[ks], sbase + ((ABQ * AST) + arow * AST + ks * 16 + k8) * 2);
        }
    }
    __syncthreads();

    float ctx[8][4];
    #pragma unroll
    for (int nt = 0; nt < 8; nt++)
        #pragma unroll
        for (int e = 0; e < 4; e++) ctx[nt][e] = 0.f;
    float mrow[2] = {-1e30f, -1e30f};
    float lrow[2] = {0.f, 0.f};

    const int nkt = 2 * qt + 2;

    uint4 rg[6];
    #define AGLD(kt_) do {                                                     \
        const __half* gt0[3] = {Kh, Vh, Vl};                                   \
        _Pragma("unroll")                                                      \
        for (int tn = 0; tn < 3; tn++)                                         \
            _Pragma("unroll")                                                  \
            for (int t = 0; t < 2; t++) {                                      \
                int u = tid + t * 256;                                         \
                int row = u >> 3, seg = u & 7;                                 \
                rg[tn * 2 + t] = *reinterpret_cast<const uint4*>(              \
                    gt0[tn] + (rowbase + (kt_) * AKV + row) * 1024             \
                            + colbase + seg * 8);                              \
            }                                                                  \
    } while (0)
    #define ASTS(buf_) do {                                                    \
        __half* sb = s + (buf_) * STAGE_H;                                     \
        _Pragma("unroll")                                                      \
        for (int tn = 0; tn < 3; tn++)                                         \
            _Pragma("unroll")                                                  \
            for (int t = 0; t < 2; t++) {                                      \
                int u = tid + t * 256;                                         \
                int row = u >> 3, seg = u & 7;                                 \
                *reinterpret_cast<uint4*>(sb + tn * KVT_H + row * AST          \
                                          + seg * 8) = rg[tn * 2 + t];         \
            }                                                                  \
    } while (0)

    AGLD(0);
    ASTS(0);
    __syncthreads();

    for (int kt = 0; kt < nkt; kt++) {
        const int buf = kt & 1;
        if (kt + 1 < nkt) AGLD(kt + 1);

        const bool skip = (kt * AKV) > (wq + 15);
        if (!skip) {
            const uint32_t kh_b = sbase + (buf * STAGE_H + 0 * KVT_H) * 2;
            const uint32_t vh_b = sbase + (buf * STAGE_H + 1 * KVT_H) * 2;
            const uint32_t vl_b = sbase + (buf * STAGE_H + 2 * KVT_H) * 2;

            // ---- S = Q K^T (2-term: Q corrected) ----
            float sv[8][4];
            #pragma unroll
            for (int nt = 0; nt < 8; nt++)
                #pragma unroll
                for (int e = 0; e < 4; e++) sv[nt][e] = 0.f;

            const int brow = lane & 15;
            const int k8   = (lane >> 4) * 8;
            #pragma unroll
            for (int ks = 0; ks < 4; ks++) {
                #pragma unroll
                for (int np = 0; np < 4; np++) {
                    uint32_t kh4[4];
                    const uint32_t off = ((np * 16 + brow) * AST + ks * 16 + k8) * 2;
                    ldsm4(kh4, kh_b + off);
                    mma_f16(sv[2 * np],     qfh[ks], kh4[0], kh4[2]);
                    mma_f16(sv[2 * np],     qfl[ks], kh4[0], kh4[2]);
                    mma_f16(sv[2 * np + 1], qfh[ks], kh4[1], kh4[3]);
                    mma_f16(sv[2 * np + 1], qfl[ks], kh4[1], kh4[3]);
                }
            }

            // ---- causal mask ----
            if (kt * AKV + AKV - 1 > wq) {
                const int qr = wq + (lane >> 2);
                #pragma unroll
                for (int nt = 0; nt < 8; nt++) {
                    const int kg0 = kt * AKV + nt * 8 + (lane & 3) * 2;
                    #pragma unroll
                    for (int e = 0; e < 4; e++) {
                        const int qg = qr + ((e >> 1) << 3);
                        const int kg = kg0 + (e & 1);
                        if (kg > qg) sv[nt][e] = -1e30f;
                    }
                }
            }

            // ---- online softmax ----
            float alpha[2];
            #pragma unroll
            for (int rr = 0; rr < 2; rr++) {
                float rmax = -1e30f;
                #pragma unroll
                for (int nt = 0; nt < 8; nt++)
                    rmax = fmaxf(rmax, fmaxf(sv[nt][2 * rr], sv[nt][2 * rr + 1]));
                rmax = fmaxf(rmax, __shfl_xor_sync(0xffffffffu, rmax, 1));
                rmax = fmaxf(rmax, __shfl_xor_sync(0xffffffffu, rmax, 2));
                const float mnew = fmaxf(mrow[rr], rmax);
                alpha[rr] = __expf(mrow[rr] - mnew);
                float rsum = 0.f;
                #pragma unroll
                for (int nt = 0; nt < 8; nt++) {
                    float p0 = __expf(sv[nt][2 * rr]     - mnew);
                    float p1 = __expf(sv[nt][2 * rr + 1] - mnew);
                    sv[nt][2 * rr] = p0; sv[nt][2 * rr + 1] = p1;
                    rsum += p0 + p1;
                }
                rsum += __shfl_xor_sync(0xffffffffu, rsum, 1);
                rsum += __shfl_xor_sync(0xffffffffu, rsum, 2);
                lrow[rr] = lrow[rr] * alpha[rr] + rsum;
                mrow[rr] = mnew;
            }
            #pragma unroll
            for (int nt = 0; nt < 8; nt++) {
                ctx[nt][0] *= alpha[0]; ctx[nt][1] *= alpha[0];
                ctx[nt][2] *= alpha[1]; ctx[nt][3] *= alpha[1];
            }

            // ---- pack P fragments (fp16 hi/lo) ----
            uint32_t pah[4][4], pal[4][4];
            #pragma unroll
            for (int t = 0; t < 4; t++) {
                #pragma unroll
                for (int h2 = 0; h2 < 4; h2++) {
                    const int nt = 2 * t + (h2 >> 1);
                    const int e0 = (h2 & 1) * 2;
                    const float a0 = sv[nt][e0], a1 = sv[nt][e0 + 1];
                    const __half h0 = __float2half_rn(a0);
                    const __half h1 = __float2half_rn(a1);
                    pah[t][h2] = pack_h2(h0, h1);
                    pal[t][h2] = pack_h2(
                        __float2half_rn(a0 - __half2float(h0)),
                        __float2half_rn(a1 - __half2float(h1)));
                }
            }

            // ---- ctx += P V (3-term) ----
            #pragma unroll
            for (int t = 0; t < 4; t++) {
                #pragma unroll
                for (int dp = 0; dp < 4; dp++) {
                    uint32_t vh4[4], vl4[4];
                    const uint32_t off =
                        ((t * 16 + (lane & 15)) * AST + dp * 16 + k8) * 2;
                    ldsm4t(vh4, vh_b + off);
                    ldsm4t(vl4, vl_b + off);
                    mma_f16(ctx[2 * dp],     pah[t], vh4[0], vh4[1]);
                    mma_f16(ctx[2 * dp],     pal[t], vh4[0], vh4[1]);
                    mma_f16(ctx[2 * dp],     pah[t], vl4[0], vl4[1]);
                    mma_f16(ctx[2 * dp + 1], pah[t], vh4[2], vh4[3]);
                    mma_f16(ctx[2 * dp + 1], pal[t], vh4[2], vh4[3]);
                    mma_f16(ctx[2 * dp + 1], pah[t], vl4[2], vl4[3]);
                }
            }
        }

        if (kt + 1 < nkt) ASTS(buf ^ 1);
        __syncthreads();
    }

    // ---- epilogue: ctx /= l, write fp16 hi/lo splits ----
    #pragma unroll
    for (int rr = 0; rr < 2; rr++) {
        const float inv = 1.f / lrow[rr];
        const size_t row = rowbase + qbase + w * 16 + (lane >> 2) + rr * 8;
        #pragma unroll
        for (int nt = 0; nt < 8; nt++) {
            const int col = colbase + nt * 8 + (lane & 3) * 2;
            const float v0 = ctx[nt][2 * rr] * inv;
            const float v1 = ctx[nt][2 * rr + 1] * inv;
            const __half h0 = __float2half_rn(v0);
            const __half h1 = __float2half_rn(v1);
            const __half l0 = __float2half_rn(v0 - __half2float(h0));
            const __half l1 = __float2half_rn(v1 - __half2float(h1));
            *reinterpret_cast<uint32_t*>(Ch + row * 1024 + col) = pack_h2(h0, h1);
            *reinterpret_cast<uint32_t*>(Cl + row * 1024 + col) = pack_h2(l0, l1);
        }
    }
    #undef AGLD
    #undef ASTS
}

// ---------------------------------------------------------------------------
// Launcher
// ---------------------------------------------------------------------------
extern "C" void kernel_launch(void* const* d_in, const int* in_sizes, int n_in,
                              void* d_out, int out_size)
{
    const float* x  = (const float*)d_in[0];
    const float* Wq = (const float*)d_in[1];
    const float* Wk = (const float*)d_in[2];
    const float* Wv = (const float*)d_in[3];
    const float* Wo = (const float*)d_in[4];
    const float* bo = (const float*)d_in[5];
    float* out = (float*)d_out;

    __half *xh, *xl, *Wt, *qhh, *qhl, *khh, *vhh, *vhl, *chh, *chl;
    cudaGetSymbolAddress((void**)&xh,  g_xh);
    cudaGetSymbolAddress((void**)&xl,  g_xl);
    cudaGetSymbolAddress((void**)&Wt,  g_Wt);
    cudaGetSymbolAddress((void**)&qhh, g_Qh);
    cudaGetSymbolAddress((void**)&qhl, g_Ql);
    cudaGetSymbolAddress((void**)&khh, g_Kh);
    cudaGetSymbolAddress((void**)&vhh, g_Vh);
    cudaGetSymbolAddress((void**)&vhl, g_Vl);
    cudaGetSymbolAddress((void**)&chh, g_Ch);
    cudaGetSymbolAddress((void**)&chl, g_Cl);

    const int n4 = MROWS * DIN / 4;

    // split x -> fp16 hi/lo
    split_half_kernel<<<(n4 + 255) / 256, 256>>>(x, xh, xl, 1.0f, n4);

    // transpose the four weight matrices to fp16 [N,K]
    dim3 tb(32, 8), tg(32, 32);
    transpose_half_kernel<<<tg, tb>>>(Wq, Wt + 0 * WELEM);
    transpose_half_kernel<<<tg, tb>>>(Wk, Wt + 1 * WELEM);
    transpose_half_kernel<<<tg, tb>>>(Wv, Wt + 2 * WELEM);
    transpose_half_kernel<<<tg, tb>>>(Wo, Wt + 3 * WELEM);

    // fused QKV GEMM (N = 3072)
    cudaFuncSetAttribute(gemm_pipe<true>,
                         cudaFuncAttributeMaxDynamicSharedMemorySize, GEMM_SMEM);
    cudaFuncSetAttribute(gemm_pipe<false>,
                         cudaFuncAttributeMaxDynamicSharedMemorySize, GEMM_SMEM);
    dim3 gq(3 * DOUT / CTN, MROWS / CTM);   // (24, 32)
    gemm_pipe<true><<<gq, 256, GEMM_SMEM>>>(xh, xl, Wt, nullptr, nullptr,
                                            qhh, qhl, khh, vhh, vhl);

    // HMMA flash attention -> fp16 hi/lo ctx
    cudaFuncSetAttribute(attn_mma, cudaFuncAttributeMaxDynamicSharedMemorySize,
                         ASMEM_B);
    dim3 attn_grid(SEQ / ABQ, BATCH * NHEADS);   // (16, 32)
    attn_mma<<<attn_grid, 256, ASMEM_B>>>(qhh, qhl, khh, vhh, vhl, chh, chl);

    // output projection (with bias)
    dim3 go(DOUT / CTN, MROWS / CTM);       // (8, 32)
    gemm_pipe<false><<<go, 256, GEMM_SMEM>>>(chh, chl, Wt + 3 * WELEM,
                                             bo, out,
                                             nullptr, nullptr, nullptr,
                                             nullptr, nullptr);
}

// round 13
// speedup vs baseline: 4.6670x; 1.3268x over previous
#include <cuda_runtime.h>
#include <cuda_bf16.h>
#include <cuda_fp16.h>
#include <cstdint>

// Problem constants
#define BATCH   2
#define SEQ     2048
#define DIN     1024
#define DOUT    1024
#define NHEADS  16
#define HDIM    64
#define MROWS   (BATCH * SEQ)        // 4096
#define WELEM   (DIN * DOUT)         // 1M

// ---------------------------------------------------------------------------
// Scratch (device globals — no runtime allocation allowed)
// ---------------------------------------------------------------------------
__device__ __half g_xh[MROWS * DIN];         // x fp16 (hi only)
__device__ __half g_Wt[4 * WELEM];           // transposed weights [N,K], fp16
__device__ __half g_Qh[MROWS * DOUT];
__device__ __half g_Ql[MROWS * DOUT];
__device__ __half g_Kh[MROWS * DOUT];        // K hi only
__device__ __half g_Vh[MROWS * DOUT];        // V hi only
__device__ __half g_Ch[MROWS * DOUT];        // ctx split hi
__device__ __half g_Cl[MROWS * DOUT];        // ctx split lo

// ---------------------------------------------------------------------------
// Warp-MMA / async-copy helpers (baseline PTX ISA, no arch-"a" features)
// ---------------------------------------------------------------------------
__device__ __forceinline__ uint32_t smem_u32(const void* p) {
    uint32_t a;
    asm("{ .reg .u64 t; cvta.to.shared.u64 t, %1; cvt.u32.u64 %0, t; }"
        : "=r"(a) : "l"(p));
    return a;
}
__device__ __forceinline__ void ldsm4(uint32_t* r, uint32_t addr) {
    asm volatile("ldmatrix.sync.aligned.m8n8.x4.shared.b16 {%0,%1,%2,%3}, [%4];"
                 : "=r"(r[0]), "=r"(r[1]), "=r"(r[2]), "=r"(r[3]) : "r"(addr));
}
__device__ __forceinline__ void ldsm4t(uint32_t* r, uint32_t addr) {
    asm volatile("ldmatrix.sync.aligned.m8n8.x4.trans.shared.b16 {%0,%1,%2,%3}, [%4];"
                 : "=r"(r[0]), "=r"(r[1]), "=r"(r[2]), "=r"(r[3]) : "r"(addr));
}
__device__ __forceinline__ void mma_f16(float* c, const uint32_t* a,
                                        uint32_t b0, uint32_t b1) {
    asm volatile(
        "mma.sync.aligned.m16n8k16.row.col.f32.f16.f16.f32 "
        "{%0,%1,%2,%3}, {%4,%5,%6,%7}, {%8,%9}, {%0,%1,%2,%3};"
        : "+f"(c[0]), "+f"(c[1]), "+f"(c[2]), "+f"(c[3])
        : "r"(a[0]), "r"(a[1]), "r"(a[2]), "r"(a[3]), "r"(b0), "r"(b1));
}
__device__ __forceinline__ void cp16(uint32_t dst, const void* src) {
    asm volatile("cp.async.cg.shared.global [%0], [%1], 16;"
                 :: "r"(dst), "l"(src));
}
#define CP_COMMIT() asm volatile("cp.async.commit_group;" ::: "memory")
#define CP_WAIT1()  asm volatile("cp.async.wait_group 1;" ::: "memory")
#define CP_WAIT0()  asm volatile("cp.async.wait_group 0;" ::: "memory")

__device__ __forceinline__ uint32_t pack_h2(__half a, __half b) {
    __half2 h = __halves2half2(a, b);
    return *reinterpret_cast<uint32_t*>(&h);
}

// ---------------------------------------------------------------------------
// Convert fp32 -> fp16
// ---------------------------------------------------------------------------
__global__ __launch_bounds__(256)
void convert_half_kernel(const float* __restrict__ in, __half* __restrict__ o, int n4)
{
    int i = blockIdx.x * blockDim.x + threadIdx.x;
    if (i >= n4) return;
    float4 v = reinterpret_cast<const float4*>(in)[i];
    uint2 p = make_uint2(pack_h2(__float2half_rn(v.x), __float2half_rn(v.y)),
                         pack_h2(__float2half_rn(v.z), __float2half_rn(v.w)));
    reinterpret_cast<uint2*>(o)[i] = p;
}

// ---------------------------------------------------------------------------
// Transpose: W [K,N] fp32 row-major -> Wt [N,K] fp16
// ---------------------------------------------------------------------------
__global__ __launch_bounds__(256)
void transpose_half_kernel(const float* __restrict__ W, __half* __restrict__ T)
{
    __shared__ float t[32][33];
    int bx = blockIdx.x * 32;   // N
    int by = blockIdx.y * 32;   // K
    int x = threadIdx.x, y = threadIdx.y;
    #pragma unroll
    for (int j = 0; j < 32; j += 8)
        t[y + j][x] = W[(size_t)(by + y + j) * DOUT + bx + x];
    __syncthreads();
    #pragma unroll
    for (int j = 0; j < 32; j += 8)
        T[(size_t)(bx + y + j) * DIN + by + x] = __float2half_rn(t[x][y + j]);
}

// ---------------------------------------------------------------------------
// cp.async-pipelined HMMA GEMM.  CTA tile 128x128, K-tile 32, 2-stage, 2 CTA/SM.
// QKV=true : 1-term fp16 (A hi only), fused N=3072; epilogue emits
//            Q hi/lo (x0.125), K hi, V hi.
// QKV=false: 2-term (A hi+lo), fp32 + bias epilogue (output projection).
// ---------------------------------------------------------------------------
#define CTM 128
#define CTN 128
#define CTK 32
#define GKIT (DIN / CTK)             // 32
#define TENB 10240                   // bytes per tensor tile (128 rows * 80 B)

template<bool QKV>
__global__ __launch_bounds__(256, 2)
void gemm_pipe(const __half* __restrict__ Ah, const __half* __restrict__ Al,
               const __half* __restrict__ Bh,
               const float* __restrict__ bias, float* __restrict__ C,
               __half* __restrict__ O0h, __half* __restrict__ O0l,
               __half* __restrict__ O1h, __half* __restrict__ O2h)
{
    constexpr int ATERMS = QKV ? 1 : 2;
    constexpr int TO_AL  = TENB;               // used iff ATERMS==2
    constexpr int TO_B   = ATERMS * TENB;
    constexpr int STAGE  = TO_B + TENB;

    extern __shared__ __align__(16) char sm_raw[];
    const uint32_t su = smem_u32(sm_raw);

    const int tid  = threadIdx.x;
    const int w    = tid >> 5;
    const int lane = tid & 31;
    const int wm   = w >> 2;            // 0..1
    const int wn   = w & 3;             // 0..3
    const int bm   = blockIdx.y * CTM;
    const int bn   = blockIdx.x * CTN;

    const int arow = wm * 64 + (lane & 15);
    const int brow = wn * 32 + (lane & 15);
    const int khalf = (lane >> 4) * 8;

    float acc[4][4][4];
    #pragma unroll
    for (int mt = 0; mt < 4; mt++)
        #pragma unroll
        for (int nt = 0; nt < 4; nt++)
            #pragma unroll
            for (int e = 0; e < 4; e++) acc[mt][nt][e] = 0.f;

    #define ISSUE(it_, buf_) do {                                              \
        const int k0_ = (it_) * CTK;                                           \
        const uint32_t sb_ = su + (buf_) * STAGE;                              \
        _Pragma("unroll")                                                      \
        for (int t = 0; t < 2; t++) {                                          \
            int u = tid + t * 256;                                             \
            int row = u >> 2, cs = u & 3;                                      \
            size_t ga = (size_t)(bm + row) * 1024 + k0_ + cs * 8;              \
            size_t gb = (size_t)(bn + row) * 1024 + k0_ + cs * 8;              \
            uint32_t off = row * 80 + cs * 16;                                 \
            cp16(sb_ + off, Ah + ga);                                          \
            if (ATERMS == 2) cp16(sb_ + TO_AL + off, Al + ga);                 \
            cp16(sb_ + TO_B + off, Bh + gb);                                   \
        }                                                                      \
    } while (0)

    ISSUE(0, 0);
    CP_COMMIT();

    for (int it = 0; it < GKIT; it++) {
        if (it + 1 < GKIT) {
            ISSUE(it + 1, (it + 1) & 1);
            CP_COMMIT();
            CP_WAIT1();
        } else {
            CP_WAIT0();
        }
        __syncthreads();

        const uint32_t sb = su + (it & 1) * STAGE;

        #pragma unroll
        for (int ks = 0; ks < 2; ks++) {
            const int kb = ks * 16 + khalf;
            uint32_t bh[8];
            ldsm4(bh + 0, sb + TO_B + (brow +  0) * 80 + kb * 2);
            ldsm4(bh + 4, sb + TO_B + (brow + 16) * 80 + kb * 2);

            #pragma unroll
            for (int mt = 0; mt < 4; mt++) {
                uint32_t ah[4], al[4];
                ldsm4(ah, sb + (arow + mt * 16) * 80 + kb * 2);
                if (ATERMS == 2)
                    ldsm4(al, sb + TO_AL + (arow + mt * 16) * 80 + kb * 2);
                #pragma unroll
                for (int nt = 0; nt < 4; nt++) {
                    const int i0 = 4 * (nt >> 1) + (nt & 1);
                    mma_f16(acc[mt][nt], ah, bh[i0], bh[i0 + 2]);
                    if (ATERMS == 2)
                        mma_f16(acc[mt][nt], al, bh[i0], bh[i0 + 2]);
                }
            }
        }
        __syncthreads();
    }
    #undef ISSUE

    const int erow = bm + wm * 64 + (lane >> 2);

    if (QKV) {
        const int tsel = bn >> 10;              // 0=Q, 1=K, 2=V
        const int cloc = (bn & 1023) + wn * 32;
        __half* Oh = (tsel == 0) ? O0h : (tsel == 1) ? O1h : O2h;
        const bool wlo = (tsel == 0);
        const float scl = (tsel == 0) ? 0.125f : 1.0f;
        #pragma unroll
        for (int nt = 0; nt < 4; nt++) {
            const int col = cloc + nt * 8 + (lane & 3) * 2;
            #pragma unroll
            for (int mt = 0; mt < 4; mt++) {
                #pragma unroll
                for (int rh = 0; rh < 2; rh++) {
                    const size_t row = (size_t)(erow + mt * 16 + rh * 8);
                    const float v0 = acc[mt][nt][2 * rh]     * scl;
                    const float v1 = acc[mt][nt][2 * rh + 1] * scl;
                    const __half h0 = __float2half_rn(v0);
                    const __half h1 = __float2half_rn(v1);
                    *reinterpret_cast<uint32_t*>(Oh + row * 1024 + col) = pack_h2(h0, h1);
                    if (wlo) {
                        const __half l0 = __float2half_rn(v0 - __half2float(h0));
                        const __half l1 = __float2half_rn(v1 - __half2float(h1));
                        *reinterpret_cast<uint32_t*>(O0l + row * 1024 + col) = pack_h2(l0, l1);
                    }
                }
            }
        }
    } else {
        #pragma unroll
        for (int nt = 0; nt < 4; nt++) {
            const int col = bn + wn * 32 + nt * 8 + (lane & 3) * 2;
            const float bx = bias ? bias[col] : 0.f;
            const float by = bias ? bias[col + 1] : 0.f;
            #pragma unroll
            for (int mt = 0; mt < 4; mt++) {
                const int r0 = erow + mt * 16;
                float2 v0 = make_float2(acc[mt][nt][0] + bx, acc[mt][nt][1] + by);
                float2 v1 = make_float2(acc[mt][nt][2] + bx, acc[mt][nt][3] + by);
                *reinterpret_cast<float2*>(C + (size_t)r0 * DOUT + col) = v0;
                *reinterpret_cast<float2*>(C + (size_t)(r0 + 8) * DOUT + col) = v1;
            }
        }
    }
}
#define GEMM_SMEM_QKV (2 * (2 * TENB))   // 40960
#define GEMM_SMEM_O   (2 * (3 * TENB))   // 61440

// ---------------------------------------------------------------------------
// HMMA flash attention.  S: 2-term (Q hi/lo, K hi).  PV: 2-term (P hi/lo, V hi).
// Epilogue: fp16 hi/lo ctx splits.
// ---------------------------------------------------------------------------
#define ABQ 128
#define AKV 64
#define AST 72
#define KVT_H (AKV * AST)               // 4608 halves
#define STAGE_H (2 * KVT_H)             // Kh | Vh
#define ASMEM_B (2 * STAGE_H * 2)       // 36864 bytes

__global__ __launch_bounds__(256, 1)
void attn_mma(const __half* __restrict__ Qh, const __half* __restrict__ Ql,
              const __half* __restrict__ Kh, const __half* __restrict__ Vh,
              __half* __restrict__ Ch, __half* __restrict__ Cl)
{
    extern __shared__ __align__(16) __half s[];
    const uint32_t sbase = smem_u32(s);

    const int tid  = threadIdx.x;
    const int w    = tid >> 5;
    const int lane = tid & 31;

    const int qt = (int)gridDim.x - 1 - (int)blockIdx.x;   // heavy first
    const int bh = blockIdx.y;
    const int b  = bh >> 4;
    const int h  = bh & 15;

    const size_t rowbase = (size_t)b * SEQ;
    const int    colbase = h * HDIM;
    const int    qbase   = qt * ABQ;
    const int    wq      = qbase + w * 16;

    // ---- stage Q hi/lo, load A fragments ----
    {
        #pragma unroll
        for (int t = 0; t < 4; t++) {
            int u = tid + t * 256;
            int row = u >> 3, seg = u & 7;
            uint4 vh4 = *reinterpret_cast<const uint4*>(
                Qh + (rowbase + qbase + row) * 1024 + colbase + seg * 8);
            uint4 vl4 = *reinterpret_cast<const uint4*>(
                Ql + (rowbase + qbase + row) * 1024 + colbase + seg * 8);
            *reinterpret_cast<uint4*>(s + row * AST + seg * 8) = vh4;
            *reinterpret_cast<uint4*>(s + ABQ * AST + row * AST + seg * 8) = vl4;
        }
    }
    __syncthreads();

    uint32_t qfh[4][4], qfl[4][4];
    {
        const int arow = w * 16 + (lane & 15);
        const int k8   = (lane >> 4) * 8;
        #pragma unroll
        for (int ks = 0; ks < 4; ks++) {
            ldsm4(qfh[ks], sbase + (arow * AST + ks * 16 + k8) * 2);
            ldsm4(qfl[ks], sbase + ((ABQ * AST) + arow * AST + ks * 16 + k8) * 2);
        }
    }
    __syncthreads();

    float ctx[8][4];
    #pragma unroll
    for (int nt = 0; nt < 8; nt++)
        #pragma unroll
        for (int e = 0; e < 4; e++) ctx[nt][e] = 0.f;
    float mrow[2] = {-1e30f, -1e30f};
    float lrow[2] = {0.f, 0.f};

    const int nkt = 2 * qt + 2;

    uint4 rg[4];
    #define AGLD(kt_) do {                                                     \
        const __half* gt0[2] = {Kh, Vh};                                       \
        _Pragma("unroll")                                                      \
        for (int tn = 0; tn < 2; tn++)                                         \
            _Pragma("unroll")                                                  \
            for (int t = 0; t < 2; t++) {                                      \
                int u = tid + t * 256;                                         \
                int row = u >> 3, seg = u & 7;                                 \
                rg[tn * 2 + t] = *reinterpret_cast<const uint4*>(              \
                    gt0[tn] + (rowbase + (kt_) * AKV + row) * 1024             \
                            + colbase + seg * 8);                              \
            }                                                                  \
    } while (0)
    #define ASTS(buf_) do {                                                    \
        __half* sb = s + (buf_) * STAGE_H;                                     \
        _Pragma("unroll")                                                      \
        for (int tn = 0; tn < 2; tn++)                                         \
            _Pragma("unroll")                                                  \
            for (int t = 0; t < 2; t++) {                                      \
                int u = tid + t * 256;                                         \
                int row = u >> 3, seg = u & 7;                                 \
                *reinterpret_cast<uint4*>(sb + tn * KVT_H + row * AST          \
                                          + seg * 8) = rg[tn * 2 + t];         \
            }                                                                  \
    } while (0)

    AGLD(0);
    ASTS(0);
    __syncthreads();

    for (int kt = 0; kt < nkt; kt++) {
        const int buf = kt & 1;
        if (kt + 1 < nkt) AGLD(kt + 1);

        const bool skip = (kt * AKV) > (wq + 15);
        if (!skip) {
            const uint32_t kh_b = sbase + (buf * STAGE_H + 0 * KVT_H) * 2;
            const uint32_t vh_b = sbase + (buf * STAGE_H + 1 * KVT_H) * 2;

            // ---- S = Q K^T (2-term: Q corrected) ----
            float sv[8][4];
            #pragma unroll
            for (int nt = 0; nt < 8; nt++)
                #pragma unroll
                for (int e = 0; e < 4; e++) sv[nt][e] = 0.f;

            const int brow = lane & 15;
            const int k8   = (lane >> 4) * 8;
            #pragma unroll
            for (int ks = 0; ks < 4; ks++) {
                #pragma unroll
                for (int np = 0; np < 4; np++) {
                    uint32_t kh4[4];
                    const uint32_t off = ((np * 16 + brow) * AST + ks * 16 + k8) * 2;
                    ldsm4(kh4, kh_b + off);
                    mma_f16(sv[2 * np],     qfh[ks], kh4[0], kh4[2]);
                    mma_f16(sv[2 * np],     qfl[ks], kh4[0], kh4[2]);
                    mma_f16(sv[2 * np + 1], qfh[ks], kh4[1], kh4[3]);
                    mma_f16(sv[2 * np + 1], qfl[ks], kh4[1], kh4[3]);
                }
            }

            // ---- causal mask ----
            if (kt * AKV + AKV - 1 > wq) {
                const int qr = wq + (lane >> 2);
                #pragma unroll
                for (int nt = 0; nt < 8; nt++) {
                    const int kg0 = kt * AKV + nt * 8 + (lane & 3) * 2;
                    #pragma unroll
                    for (int e = 0; e < 4; e++) {
                        const int qg = qr + ((e >> 1) << 3);
                        const int kg = kg0 + (e & 1);
                        if (kg > qg) sv[nt][e] = -1e30f;
                    }
                }
            }

            // ---- online softmax ----
            float alpha[2];
            #pragma unroll
            for (int rr = 0; rr < 2; rr++) {
                float rmax = -1e30f;
                #pragma unroll
                for (int nt = 0; nt < 8; nt++)
                    rmax = fmaxf(rmax, fmaxf(sv[nt][2 * rr], sv[nt][2 * rr + 1]));
                rmax = fmaxf(rmax, __shfl_xor_sync(0xffffffffu, rmax, 1));
                rmax = fmaxf(rmax, __shfl_xor_sync(0xffffffffu, rmax, 2));
                const float mnew = fmaxf(mrow[rr], rmax);
                alpha[rr] = __expf(mrow[rr] - mnew);
                float rsum = 0.f;
                #pragma unroll
                for (int nt = 0; nt < 8; nt++) {
                    float p0 = __expf(sv[nt][2 * rr]     - mnew);
                    float p1 = __expf(sv[nt][2 * rr + 1] - mnew);
                    sv[nt][2 * rr] = p0; sv[nt][2 * rr + 1] = p1;
                    rsum += p0 + p1;
                }
                rsum += __shfl_xor_sync(0xffffffffu, rsum, 1);
                rsum += __shfl_xor_sync(0xffffffffu, rsum, 2);
                lrow[rr] = lrow[rr] * alpha[rr] + rsum;
                mrow[rr] = mnew;
            }
            #pragma unroll
            for (int nt = 0; nt < 8; nt++) {
                ctx[nt][0] *= alpha[0]; ctx[nt][1] *= alpha[0];
                ctx[nt][2] *= alpha[1]; ctx[nt][3] *= alpha[1];
            }

            // ---- pack P fragments (fp16 hi/lo) ----
            uint32_t pah[4][4], pal[4][4];
            #pragma unroll
            for (int t = 0; t < 4; t++) {
                #pragma unroll
                for (int h2 = 0; h2 < 4; h2++) {
                    const int nt = 2 * t + (h2 >> 1);
                    const int e0 = (h2 & 1) * 2;
                    const float a0 = sv[nt][e0], a1 = sv[nt][e0 + 1];
                    const __half h0 = __float2half_rn(a0);
                    const __half h1 = __float2half_rn(a1);
                    pah[t][h2] = pack_h2(h0, h1);
                    pal[t][h2] = pack_h2(
                        __float2half_rn(a0 - __half2float(h0)),
                        __float2half_rn(a1 - __half2float(h1)));
                }
            }

            // ---- ctx += P V (2-term: P corrected, V hi) ----
            #pragma unroll
            for (int t = 0; t < 4; t++) {
                #pragma unroll
                for (int dp = 0; dp < 4; dp++) {
                    uint32_t vh4[4];
                    const uint32_t off =
                        ((t * 16 + (lane & 15)) * AST + dp * 16 + k8) * 2;
                    ldsm4t(vh4, vh_b + off);
                    mma_f16(ctx[2 * dp],     pah[t], vh4[0], vh4[1]);
                    mma_f16(ctx[2 * dp],     pal[t], vh4[0], vh4[1]);
                    mma_f16(ctx[2 * dp + 1], pah[t], vh4[2], vh4[3]);
                    mma_f16(ctx[2 * dp + 1], pal[t], vh4[2], vh4[3]);
                }
            }
        }

        if (kt + 1 < nkt) ASTS(buf ^ 1);
        __syncthreads();
    }

    // ---- epilogue: ctx /= l, write fp16 hi/lo splits ----
    #pragma unroll
    for (int rr = 0; rr < 2; rr++) {
        const float inv = 1.f / lrow[rr];
        const size_t row = rowbase + qbase + w * 16 + (lane >> 2) + rr * 8;
        #pragma unroll
        for (int nt = 0; nt < 8; nt++) {
            const int col = colbase + nt * 8 + (lane & 3) * 2;
            const float v0 = ctx[nt][2 * rr] * inv;
            const float v1 = ctx[nt][2 * rr + 1] * inv;
            const __half h0 = __float2half_rn(v0);
            const __half h1 = __float2half_rn(v1);
            const __half l0 = __float2half_rn(v0 - __half2float(h0));
            const __half l1 = __float2half_rn(v1 - __half2float(h1));
            *reinterpret_cast<uint32_t*>(Ch + row * 1024 + col) = pack_h2(h0, h1);
            *reinterpret_cast<uint32_t*>(Cl + row * 1024 + col) = pack_h2(l0, l1);
        }
    }
    #undef AGLD
    #undef ASTS
}

// ---------------------------------------------------------------------------
// Launcher
// ---------------------------------------------------------------------------
extern "C" void kernel_launch(void* const* d_in, const int* in_sizes, int n_in,
                              void* d_out, int out_size)
{
    const float* x  = (const float*)d_in[0];
    const float* Wq = (const float*)d_in[1];
    const float* Wk = (const float*)d_in[2];
    const float* Wv = (const float*)d_in[3];
    const float* Wo = (const float*)d_in[4];
    const float* bo = (const float*)d_in[5];
    float* out = (float*)d_out;

    __half *xh, *Wt, *qhh, *qhl, *khh, *vhh, *chh, *chl;
    cudaGetSymbolAddress((void**)&xh,  g_xh);
    cudaGetSymbolAddress((void**)&Wt,  g_Wt);
    cudaGetSymbolAddress((void**)&qhh, g_Qh);
    cudaGetSymbolAddress((void**)&qhl, g_Ql);
    cudaGetSymbolAddress((void**)&khh, g_Kh);
    cudaGetSymbolAddress((void**)&vhh, g_Vh);
    cudaGetSymbolAddress((void**)&chh, g_Ch);
    cudaGetSymbolAddress((void**)&chl, g_Cl);

    const int n4 = MROWS * DIN / 4;

    // convert x -> fp16
    convert_half_kernel<<<(n4 + 255) / 256, 256>>>(x, xh, n4);

    // transpose the four weight matrices to fp16 [N,K]
    dim3 tb(32, 8), tg(32, 32);
    transpose_half_kernel<<<tg, tb>>>(Wq, Wt + 0 * WELEM);
    transpose_half_kernel<<<tg, tb>>>(Wk, Wt + 1 * WELEM);
    transpose_half_kernel<<<tg, tb>>>(Wv, Wt + 2 * WELEM);
    transpose_half_kernel<<<tg, tb>>>(Wo, Wt + 3 * WELEM);

    // fused QKV GEMM (N = 3072), 1-term fp16
    cudaFuncSetAttribute(gemm_pipe<true>,
                         cudaFuncAttributeMaxDynamicSharedMemorySize, GEMM_SMEM_QKV);
    cudaFuncSetAttribute(gemm_pipe<false>,
                         cudaFuncAttributeMaxDynamicSharedMemorySize, GEMM_SMEM_O);
    dim3 gq(3 * DOUT / CTN, MROWS / CTM);   // (24, 32)
    gemm_pipe<true><<<gq, 256, GEMM_SMEM_QKV>>>(xh, nullptr, Wt, nullptr, nullptr,
                                                qhh, qhl, khh, vhh);

    // HMMA flash attention -> fp16 hi/lo ctx
    cudaFuncSetAttribute(attn_mma, cudaFuncAttributeMaxDynamicSharedMemorySize,
                         ASMEM_B);
    dim3 attn_grid(SEQ / ABQ, BATCH * NHEADS);   // (16, 32)
    attn_mma<<<attn_grid, 256, ASMEM_B>>>(qhh, qhl, khh, vhh, chh, chl);

    // output projection (2-term ctx, with bias)
    dim3 go(DOUT / CTN, MROWS / CTM);       // (8, 32)
    gemm_pipe<false><<<go, 256, GEMM_SMEM_O>>>(chh, chl, Wt + 3 * WELEM,
                                               bo, out,
                                               nullptr, nullptr, nullptr, nullptr);
}

// round 14
// speedup vs baseline: 5.4590x; 1.1697x over previous
#include <cuda_runtime.h>
#include <cuda_bf16.h>
#include <cuda_fp16.h>
#include <cstdint>

// Problem constants
#define BATCH   2
#define SEQ     2048
#define DIN     1024
#define DOUT    1024
#define NHEADS  16
#define HDIM    64
#define MROWS   (BATCH * SEQ)        // 4096
#define WELEM   (DIN * DOUT)         // 1M

// ---------------------------------------------------------------------------
// Scratch (device globals — no runtime allocation allowed)
// ---------------------------------------------------------------------------
__device__ __half g_xh[MROWS * DIN];         // x fp16
__device__ __half g_Wt[4 * WELEM];           // transposed weights [N,K], fp16
__device__ __half g_Qh[MROWS * DOUT];
__device__ __half g_Ql[MROWS * DOUT];        // Q lo (S stays 2-term)
__device__ __half g_Kh[MROWS * DOUT];        // K hi only
__device__ __half g_Vh[MROWS * DOUT];        // V hi only
__device__ __half g_Ch[MROWS * DOUT];        // ctx fp16 (hi only)

// ---------------------------------------------------------------------------
// Warp-MMA / async-copy helpers (baseline PTX ISA, no arch-"a" features)
// ---------------------------------------------------------------------------
__device__ __forceinline__ uint32_t smem_u32(const void* p) {
    uint32_t a;
    asm("{ .reg .u64 t; cvta.to.shared.u64 t, %1; cvt.u32.u64 %0, t; }"
        : "=r"(a) : "l"(p));
    return a;
}
__device__ __forceinline__ void ldsm4(uint32_t* r, uint32_t addr) {
    asm volatile("ldmatrix.sync.aligned.m8n8.x4.shared.b16 {%0,%1,%2,%3}, [%4];"
                 : "=r"(r[0]), "=r"(r[1]), "=r"(r[2]), "=r"(r[3]) : "r"(addr));
}
__device__ __forceinline__ void ldsm4t(uint32_t* r, uint32_t addr) {
    asm volatile("ldmatrix.sync.aligned.m8n8.x4.trans.shared.b16 {%0,%1,%2,%3}, [%4];"
                 : "=r"(r[0]), "=r"(r[1]), "=r"(r[2]), "=r"(r[3]) : "r"(addr));
}
__device__ __forceinline__ void mma_f16(float* c, const uint32_t* a,
                                        uint32_t b0, uint32_t b1) {
    asm volatile(
        "mma.sync.aligned.m16n8k16.row.col.f32.f16.f16.f32 "
        "{%0,%1,%2,%3}, {%4,%5,%6,%7}, {%8,%9}, {%0,%1,%2,%3};"
        : "+f"(c[0]), "+f"(c[1]), "+f"(c[2]), "+f"(c[3])
        : "r"(a[0]), "r"(a[1]), "r"(a[2]), "r"(a[3]), "r"(b0), "r"(b1));
}
__device__ __forceinline__ void cp16(uint32_t dst, const void* src) {
    asm volatile("cp.async.cg.shared.global [%0], [%1], 16;"
                 :: "r"(dst), "l"(src));
}
#define CP_COMMIT() asm volatile("cp.async.commit_group;" ::: "memory")
#define CP_WAIT1()  asm volatile("cp.async.wait_group 1;" ::: "memory")
#define CP_WAIT0()  asm volatile("cp.async.wait_group 0;" ::: "memory")

__device__ __forceinline__ uint32_t pack_h2(__half a, __half b) {
    __half2 h = __halves2half2(a, b);
    return *reinterpret_cast<uint32_t*>(&h);
}

// ---------------------------------------------------------------------------
// Convert fp32 -> fp16
// ---------------------------------------------------------------------------
__global__ __launch_bounds__(256)
void convert_half_kernel(const float* __restrict__ in, __half* __restrict__ o, int n4)
{
    int i = blockIdx.x * blockDim.x + threadIdx.x;
    if (i >= n4) return;
    float4 v = reinterpret_cast<const float4*>(in)[i];
    uint2 p = make_uint2(pack_h2(__float2half_rn(v.x), __float2half_rn(v.y)),
                         pack_h2(__float2half_rn(v.z), __float2half_rn(v.w)));
    reinterpret_cast<uint2*>(o)[i] = p;
}

// ---------------------------------------------------------------------------
// Transpose: W [K,N] fp32 row-major -> Wt [N,K] fp16 (4 matrices via z)
// ---------------------------------------------------------------------------
__global__ __launch_bounds__(256)
void transpose_half_kernel(const float* const* __restrict__ Ws,
                           __half* __restrict__ T)
{
    __shared__ float t[32][33];
    const float* W = Ws[blockIdx.z];
    __half* To = T + (size_t)blockIdx.z * WELEM;
    int bx = blockIdx.x * 32;   // N
    int by = blockIdx.y * 32;   // K
    int x = threadIdx.x, y = threadIdx.y;
    #pragma unroll
    for (int j = 0; j < 32; j += 8)
        t[y + j][x] = W[(size_t)(by + y + j) * DOUT + bx + x];
    __syncthreads();
    #pragma unroll
    for (int j = 0; j < 32; j += 8)
        To[(size_t)(bx + y + j) * DIN + by + x] = __float2half_rn(t[x][y + j]);
}
__device__ const float* g_Wptrs[4];
__global__ void set_wptrs_kernel(const float* a, const float* b,
                                 const float* c, const float* d)
{
    g_Wptrs[0] = a; g_Wptrs[1] = b; g_Wptrs[2] = c; g_Wptrs[3] = d;
}

// ---------------------------------------------------------------------------
// cp.async-pipelined HMMA GEMM, 1-term fp16.  128x128x32, 2-stage, 2 CTA/SM.
// QKV=true : fused N=3072; epilogue emits Q hi/lo (x0.125), K hi, V hi.
// QKV=false: fp32 + bias epilogue (output projection).
// ---------------------------------------------------------------------------
#define CTM 128
#define CTN 128
#define CTK 32
#define GKIT (DIN / CTK)             // 32
#define TENB 10240                   // bytes per tensor tile (128 rows * 80 B)
#define TO_B TENB
#define STAGE (2 * TENB)
#define GEMM_SMEM (2 * STAGE)        // 40960

template<bool QKV>
__global__ __launch_bounds__(256, 2)
void gemm_pipe(const __half* __restrict__ Ah, const __half* __restrict__ Bh,
               const float* __restrict__ bias, float* __restrict__ C,
               __half* __restrict__ O0h, __half* __restrict__ O0l,
               __half* __restrict__ O1h, __half* __restrict__ O2h)
{
    extern __shared__ __align__(16) char sm_raw[];
    const uint32_t su = smem_u32(sm_raw);

    const int tid  = threadIdx.x;
    const int w    = tid >> 5;
    const int lane = tid & 31;
    const int wm   = w >> 2;            // 0..1
    const int wn   = w & 3;             // 0..3
    const int bm   = blockIdx.y * CTM;
    const int bn   = blockIdx.x * CTN;

    const int arow = wm * 64 + (lane & 15);
    const int brow = wn * 32 + (lane & 15);
    const int khalf = (lane >> 4) * 8;

    float acc[4][4][4];
    #pragma unroll
    for (int mt = 0; mt < 4; mt++)
        #pragma unroll
        for (int nt = 0; nt < 4; nt++)
            #pragma unroll
            for (int e = 0; e < 4; e++) acc[mt][nt][e] = 0.f;

    #define ISSUE(it_, buf_) do {                                              \
        const int k0_ = (it_) * CTK;                                           \
        const uint32_t sb_ = su + (buf_) * STAGE;                              \
        _Pragma("unroll")                                                      \
        for (int t = 0; t < 2; t++) {                                          \
            int u = tid + t * 256;                                             \
            int row = u >> 2, cs = u & 3;                                      \
            size_t ga = (size_t)(bm + row) * 1024 + k0_ + cs * 8;              \
            size_t gb = (size_t)(bn + row) * 1024 + k0_ + cs * 8;              \
            uint32_t off = row * 80 + cs * 16;                                 \
            cp16(sb_ + off, Ah + ga);                                          \
            cp16(sb_ + TO_B + off, Bh + gb);                                   \
        }                                                                      \
    } while (0)

    ISSUE(0, 0);
    CP_COMMIT();

    for (int it = 0; it < GKIT; it++) {
        if (it + 1 < GKIT) {
            ISSUE(it + 1, (it + 1) & 1);
            CP_COMMIT();
            CP_WAIT1();
        } else {
            CP_WAIT0();
        }
        __syncthreads();

        const uint32_t sb = su + (it & 1) * STAGE;

        #pragma unroll
        for (int ks = 0; ks < 2; ks++) {
            const int kb = ks * 16 + khalf;
            uint32_t bh[8];
            ldsm4(bh + 0, sb + TO_B + (brow +  0) * 80 + kb * 2);
            ldsm4(bh + 4, sb + TO_B + (brow + 16) * 80 + kb * 2);

            #pragma unroll
            for (int mt = 0; mt < 4; mt++) {
                uint32_t ah[4];
                ldsm4(ah, sb + (arow + mt * 16) * 80 + kb * 2);
                #pragma unroll
                for (int nt = 0; nt < 4; nt++) {
                    const int i0 = 4 * (nt >> 1) + (nt & 1);
                    mma_f16(acc[mt][nt], ah, bh[i0], bh[i0 + 2]);
                }
            }
        }
        __syncthreads();
    }
    #undef ISSUE

    const int erow = bm + wm * 64 + (lane >> 2);

    if (QKV) {
        const int tsel = bn >> 10;              // 0=Q, 1=K, 2=V
        const int cloc = (bn & 1023) + wn * 32;
        __half* Oh = (tsel == 0) ? O0h : (tsel == 1) ? O1h : O2h;
        const bool wlo = (tsel == 0);
        const float scl = (tsel == 0) ? 0.125f : 1.0f;
        #pragma unroll
        for (int nt = 0; nt < 4; nt++) {
            const int col = cloc + nt * 8 + (lane & 3) * 2;
            #pragma unroll
            for (int mt = 0; mt < 4; mt++) {
                #pragma unroll
                for (int rh = 0; rh < 2; rh++) {
                    const size_t row = (size_t)(erow + mt * 16 + rh * 8);
                    const float v0 = acc[mt][nt][2 * rh]     * scl;
                    const float v1 = acc[mt][nt][2 * rh + 1] * scl;
                    const __half h0 = __float2half_rn(v0);
                    const __half h1 = __float2half_rn(v1);
                    *reinterpret_cast<uint32_t*>(Oh + row * 1024 + col) = pack_h2(h0, h1);
                    if (wlo) {
                        const __half l0 = __float2half_rn(v0 - __half2float(h0));
                        const __half l1 = __float2half_rn(v1 - __half2float(h1));
                        *reinterpret_cast<uint32_t*>(O0l + row * 1024 + col) = pack_h2(l0, l1);
                    }
                }
            }
        }
    } else {
        #pragma unroll
        for (int nt = 0; nt < 4; nt++) {
            const int col = bn + wn * 32 + nt * 8 + (lane & 3) * 2;
            const float bx = bias ? bias[col] : 0.f;
            const float by = bias ? bias[col + 1] : 0.f;
            #pragma unroll
            for (int mt = 0; mt < 4; mt++) {
                const int r0 = erow + mt * 16;
                float2 v0 = make_float2(acc[mt][nt][0] + bx, acc[mt][nt][1] + by);
                float2 v1 = make_float2(acc[mt][nt][2] + bx, acc[mt][nt][3] + by);
                *reinterpret_cast<float2*>(C + (size_t)r0 * DOUT + col) = v0;
                *reinterpret_cast<float2*>(C + (size_t)(r0 + 8) * DOUT + col) = v1;
            }
        }
    }
}

// ---------------------------------------------------------------------------
// HMMA flash attention.  S: 2-term (Q hi/lo, K hi).  PV: 1-term (P hi, V hi).
// Epilogue: fp16 ctx (hi only).
// ---------------------------------------------------------------------------
#define ABQ 128
#define AKV 64
#define AST 72
#define KVT_H (AKV * AST)               // 4608 halves
#define STAGE_H (2 * KVT_H)             // Kh | Vh
#define ASMEM_B (2 * STAGE_H * 2)       // 36864 bytes

__global__ __launch_bounds__(256, 1)
void attn_mma(const __half* __restrict__ Qh, const __half* __restrict__ Ql,
              const __half* __restrict__ Kh, const __half* __restrict__ Vh,
              __half* __restrict__ Ch)
{
    extern __shared__ __align__(16) __half s[];
    const uint32_t sbase = smem_u32(s);

    const int tid  = threadIdx.x;
    const int w    = tid >> 5;
    const int lane = tid & 31;

    const int qt = (int)gridDim.x - 1 - (int)blockIdx.x;   // heavy first
    const int bh = blockIdx.y;
    const int b  = bh >> 4;
    const int h  = bh & 15;

    const size_t rowbase = (size_t)b * SEQ;
    const int    colbase = h * HDIM;
    const int    qbase   = qt * ABQ;
    const int    wq      = qbase + w * 16;

    // ---- stage Q hi/lo, load A fragments ----
    {
        #pragma unroll
        for (int t = 0; t < 4; t++) {
            int u = tid + t * 256;
            int row = u >> 3, seg = u & 7;
            uint4 vh4 = *reinterpret_cast<const uint4*>(
                Qh + (rowbase + qbase + row) * 1024 + colbase + seg * 8);
            uint4 vl4 = *reinterpret_cast<const uint4*>(
                Ql + (rowbase + qbase + row) * 1024 + colbase + seg * 8);
            *reinterpret_cast<uint4*>(s + row * AST + seg * 8) = vh4;
            *reinterpret_cast<uint4*>(s + ABQ * AST + row * AST + seg * 8) = vl4;
        }
    }
    __syncthreads();

    uint32_t qfh[4][4], qfl[4][4];
    {
        const int arow = w * 16 + (lane & 15);
        const int k8   = (lane >> 4) * 8;
        #pragma unroll
        for (int ks = 0; ks < 4; ks++) {
            ldsm4(qfh[ks], sbase + (arow * AST + ks * 16 + k8) * 2);
            ldsm4(qfl[ks], sbase + ((ABQ * AST) + arow * AST + ks * 16 + k8) * 2);
        }
    }
    __syncthreads();

    float ctx[8][4];
    #pragma unroll
    for (int nt = 0; nt < 8; nt++)
        #pragma unroll
        for (int e = 0; e < 4; e++) ctx[nt][e] = 0.f;
    float mrow[2] = {-1e30f, -1e30f};
    float lrow[2] = {0.f, 0.f};

    const int nkt = 2 * qt + 2;

    uint4 rg[4];
    #define AGLD(kt_) do {                                                     \
        const __half* gt0[2] = {Kh, Vh};                                       \
        _Pragma("unroll")                                                      \
        for (int tn = 0; tn < 2; tn++)                                         \
            _Pragma("unroll")                                                  \
            for (int t = 0; t < 2; t++) {                                      \
                int u = tid + t * 256;                                         \
                int row = u >> 3, seg = u & 7;                                 \
                rg[tn * 2 + t] = *reinterpret_cast<const uint4*>(              \
                    gt0[tn] + (rowbase + (kt_) * AKV + row) * 1024             \
                            + colbase + seg * 8);                              \
            }                                                                  \
    } while (0)
    #define ASTS(buf_) do {                                                    \
        __half* sb = s + (buf_) * STAGE_H;                                     \
        _Pragma("unroll")                                                      \
        for (int tn = 0; tn < 2; tn++)                                         \
            _Pragma("unroll")                                                  \
            for (int t = 0; t < 2; t++) {                                      \
                int u = tid + t * 256;                                         \
                int row = u >> 3, seg = u & 7;                                 \
                *reinterpret_cast<uint4*>(sb + tn * KVT_H + row * AST          \
                                          + seg * 8) = rg[tn * 2 + t];         \
            }                                                                  \
    } while (0)

    AGLD(0);
    ASTS(0);
    __syncthreads();

    for (int kt = 0; kt < nkt; kt++) {
        const int buf = kt & 1;
        if (kt + 1 < nkt) AGLD(kt + 1);

        const bool skip = (kt * AKV) > (wq + 15);
        if (!skip) {
            const uint32_t kh_b = sbase + (buf * STAGE_H + 0 * KVT_H) * 2;
            const uint32_t vh_b = sbase + (buf * STAGE_H + 1 * KVT_H) * 2;

            // ---- S = Q K^T (2-term: Q corrected) ----
            float sv[8][4];
            #pragma unroll
            for (int nt = 0; nt < 8; nt++)
                #pragma unroll
                for (int e = 0; e < 4; e++) sv[nt][e] = 0.f;

            const int brow = lane & 15;
            const int k8   = (lane >> 4) * 8;
            #pragma unroll
            for (int ks = 0; ks < 4; ks++) {
                #pragma unroll
                for (int np = 0; np < 4; np++) {
                    uint32_t kh4[4];
                    const uint32_t off = ((np * 16 + brow) * AST + ks * 16 + k8) * 2;
                    ldsm4(kh4, kh_b + off);
                    mma_f16(sv[2 * np],     qfh[ks], kh4[0], kh4[2]);
                    mma_f16(sv[2 * np],     qfl[ks], kh4[0], kh4[2]);
                    mma_f16(sv[2 * np + 1], qfh[ks], kh4[1], kh4[3]);
                    mma_f16(sv[2 * np + 1], qfl[ks], kh4[1], kh4[3]);
                }
            }

            // ---- causal mask ----
            if (kt * AKV + AKV - 1 > wq) {
                const int qr = wq + (lane >> 2);
                #pragma unroll
                for (int nt = 0; nt < 8; nt++) {
                    const int kg0 = kt * AKV + nt * 8 + (lane & 3) * 2;
                    #pragma unroll
                    for (int e = 0; e < 4; e++) {
                        const int qg = qr + ((e >> 1) << 3);
                        const int kg = kg0 + (e & 1);
                        if (kg > qg) sv[nt][e] = -1e30f;
                    }
                }
            }

            // ---- online softmax ----
            float alpha[2];
            #pragma unroll
            for (int rr = 0; rr < 2; rr++) {
                float rmax = -1e30f;
                #pragma unroll
                for (int nt = 0; nt < 8; nt++)
                    rmax = fmaxf(rmax, fmaxf(sv[nt][2 * rr], sv[nt][2 * rr + 1]));
                rmax = fmaxf(rmax, __shfl_xor_sync(0xffffffffu, rmax, 1));
                rmax = fmaxf(rmax, __shfl_xor_sync(0xffffffffu, rmax, 2));
                const float mnew = fmaxf(mrow[rr], rmax);
                alpha[rr] = __expf(mrow[rr] - mnew);
                float rsum = 0.f;
                #pragma unroll
                for (int nt = 0; nt < 8; nt++) {
                    float p0 = __expf(sv[nt][2 * rr]     - mnew);
                    float p1 = __expf(sv[nt][2 * rr + 1] - mnew);
                    sv[nt][2 * rr] = p0; sv[nt][2 * rr + 1] = p1;
                    rsum += p0 + p1;
                }
                rsum += __shfl_xor_sync(0xffffffffu, rsum, 1);
                rsum += __shfl_xor_sync(0xffffffffu, rsum, 2);
                lrow[rr] = lrow[rr] * alpha[rr] + rsum;
                mrow[rr] = mnew;
            }
            #pragma unroll
            for (int nt = 0; nt < 8; nt++) {
                ctx[nt][0] *= alpha[0]; ctx[nt][1] *= alpha[0];
                ctx[nt][2] *= alpha[1]; ctx[nt][3] *= alpha[1];
            }

            // ---- pack P fragments (fp16 hi only) ----
            uint32_t pah[4][4];
            #pragma unroll
            for (int t = 0; t < 4; t++) {
                #pragma unroll
                for (int h2 = 0; h2 < 4; h2++) {
                    const int nt = 2 * t + (h2 >> 1);
                    const int e0 = (h2 & 1) * 2;
                    pah[t][h2] = pack_h2(__float2half_rn(sv[nt][e0]),
                                         __float2half_rn(sv[nt][e0 + 1]));
                }
            }

            // ---- ctx += P V (1-term) ----
            #pragma unroll
            for (int t = 0; t < 4; t++) {
                #pragma unroll
                for (int dp = 0; dp < 4; dp++) {
                    uint32_t vh4[4];
                    const uint32_t off =
                        ((t * 16 + (lane & 15)) * AST + dp * 16 + k8) * 2;
                    ldsm4t(vh4, vh_b + off);
                    mma_f16(ctx[2 * dp],     pah[t], vh4[0], vh4[1]);
                    mma_f16(ctx[2 * dp + 1], pah[t], vh4[2], vh4[3]);
                }
            }
        }

        if (kt + 1 < nkt) ASTS(buf ^ 1);
        __syncthreads();
    }

    // ---- epilogue: ctx /= l, write fp16 hi ----
    #pragma unroll
    for (int rr = 0; rr < 2; rr++) {
        const float inv = 1.f / lrow[rr];
        const size_t row = rowbase + qbase + w * 16 + (lane >> 2) + rr * 8;
        #pragma unroll
        for (int nt = 0; nt < 8; nt++) {
            const int col = colbase + nt * 8 + (lane & 3) * 2;
            *reinterpret_cast<uint32_t*>(Ch + row * 1024 + col) =
                pack_h2(__float2half_rn(ctx[nt][2 * rr] * inv),
                        __float2half_rn(ctx[nt][2 * rr + 1] * inv));
        }
    }
    #undef AGLD
    #undef ASTS
}

// ---------------------------------------------------------------------------
// Launcher
// ---------------------------------------------------------------------------
extern "C" void kernel_launch(void* const* d_in, const int* in_sizes, int n_in,
                              void* d_out, int out_size)
{
    const float* x  = (const float*)d_in[0];
    const float* Wq = (const float*)d_in[1];
    const float* Wk = (const float*)d_in[2];
    const float* Wv = (const float*)d_in[3];
    const float* Wo = (const float*)d_in[4];
    const float* bo = (const float*)d_in[5];
    float* out = (float*)d_out;

    __half *xh, *Wt, *qhh, *qhl, *khh, *vhh, *chh;
    cudaGetSymbolAddress((void**)&xh,  g_xh);
    cudaGetSymbolAddress((void**)&Wt,  g_Wt);
    cudaGetSymbolAddress((void**)&qhh, g_Qh);
    cudaGetSymbolAddress((void**)&qhl, g_Ql);
    cudaGetSymbolAddress((void**)&khh, g_Kh);
    cudaGetSymbolAddress((void**)&vhh, g_Vh);
    cudaGetSymbolAddress((void**)&chh, g_Ch);
    const float** wptrs;
    cudaGetSymbolAddress((void**)&wptrs, g_Wptrs);

    const int n4 = MROWS * DIN / 4;

    // convert x -> fp16
    convert_half_kernel<<<(n4 + 255) / 256, 256>>>(x, xh, n4);

    // transpose the four weight matrices to fp16 [N,K] (one launch)
    set_wptrs_kernel<<<1, 1>>>(Wq, Wk, Wv, Wo);
    dim3 tb(32, 8), tg(32, 32, 4);
    transpose_half_kernel<<<tg, tb>>>(wptrs, Wt);

    // fused QKV GEMM (N = 3072), 1-term fp16
    cudaFuncSetAttribute(gemm_pipe<true>,
                         cudaFuncAttributeMaxDynamicSharedMemorySize, GEMM_SMEM);
    cudaFuncSetAttribute(gemm_pipe<false>,
                         cudaFuncAttributeMaxDynamicSharedMemorySize, GEMM_SMEM);
    dim3 gq(3 * DOUT / CTN, MROWS / CTM);   // (24, 32)
    gemm_pipe<true><<<gq, 256, GEMM_SMEM>>>(xh, Wt, nullptr, nullptr,
                                            qhh, qhl, khh, vhh);

    // HMMA flash attention -> fp16 ctx
    cudaFuncSetAttribute(attn_mma, cudaFuncAttributeMaxDynamicSharedMemorySize,
                         ASMEM_B);
    dim3 attn_grid(SEQ / ABQ, BATCH * NHEADS);   // (16, 32)
    attn_mma<<<attn_grid, 256, ASMEM_B>>>(qhh, qhl, khh, vhh, chh);

    // output projection (1-term ctx, with bias)
    dim3 go(DOUT / CTN, MROWS / CTM);       // (8, 32)
    gemm_pipe<false><<<go, 256, GEMM_SMEM>>>(chh, Wt + 3 * WELEM,
                                             bo, out,
                                             nullptr, nullptr, nullptr, nullptr);
}